// round 14
// baseline (speedup 1.0000x reference)
#include <cuda_runtime.h>
#include <cuda_fp16.h>
#include <math.h>
#include <math_constants.h>
#include <stdint.h>

// Problem constants
#define BB    4
#define NN    2048
#define CC    512
#define HH    8
#define DH    64
#define HID   2048
#define MROWS (BB * NN)   // 8192
#define C3    (3 * CC)    // 1536
#define MB2   1024        // rows per half-batch chunk

// ---------------------------------------------------------------------------
// Device scratch
// ---------------------------------------------------------------------------
__device__ float g_x1 [MROWS * CC];

__device__ __half g_qv[MROWS * C3];
__device__ __half g_h1[MROWS * CC];
__device__ __half g_at[MROWS * CC];
__device__ __half g_h2[MROWS * CC];
__device__ __half g_hd[MROWS * HID];

__device__ __half g_wq[C3 * CC];
__device__ __half g_wp[CC * CC];
__device__ __half g_w1[HID * CC];
__device__ __half g_w2[CC * HID];

// ---------------------------------------------------------------------------
// PTX helpers
// ---------------------------------------------------------------------------
__device__ __forceinline__ uint32_t smem_u32(const void* p) {
    uint32_t a;
    asm("{ .reg .u64 t; cvta.to.shared.u64 t, %1; cvt.u32.u64 %0, t; }"
        : "=r"(a) : "l"(p));
    return a;
}

#define CP16(dst, src)                                                        \
    asm volatile("cp.async.cg.shared.global [%0], [%1], 16;"                  \
                 :: "r"(dst), "l"(src))
#define CP4(dst, src)                                                         \
    asm volatile("cp.async.ca.shared.global [%0], [%1], 4;"                   \
                 :: "r"(dst), "l"(src))
#define CP_COMMIT() asm volatile("cp.async.commit_group;" ::: "memory")
#define CP_WAIT1()  asm volatile("cp.async.wait_group 1;" ::: "memory")
#define CP_WAIT0()  asm volatile("cp.async.wait_group 0;" ::: "memory")

__device__ __forceinline__ void ldsm4(uint32_t* r, uint32_t addr) {
    asm volatile("ldmatrix.sync.aligned.m8n8.x4.shared.b16 {%0,%1,%2,%3}, [%4];"
                 : "=r"(r[0]), "=r"(r[1]), "=r"(r[2]), "=r"(r[3]) : "r"(addr));
}

__device__ __forceinline__ void ldsm4t(uint32_t* r, uint32_t addr) {
    asm volatile("ldmatrix.sync.aligned.m8n8.x4.trans.shared.b16 {%0,%1,%2,%3}, [%4];"
                 : "=r"(r[0]), "=r"(r[1]), "=r"(r[2]), "=r"(r[3]) : "r"(addr));
}

__device__ __forceinline__ void mma16816(float* d, const uint32_t* a,
                                         uint32_t b0, uint32_t b1) {
    asm volatile(
        "mma.sync.aligned.m16n8k16.row.col.f32.f16.f16.f32 "
        "{%0,%1,%2,%3}, {%4,%5,%6,%7}, {%8,%9}, {%0,%1,%2,%3};"
        : "+f"(d[0]), "+f"(d[1]), "+f"(d[2]), "+f"(d[3])
        : "r"(a[0]), "r"(a[1]), "r"(a[2]), "r"(a[3]), "r"(b0), "r"(b1));
}

__device__ __forceinline__ uint32_t sw128(uint32_t off) {
    return off ^ ((off >> 3) & 0x70u);
}

__device__ __forceinline__ uint32_t pack_h2(float a, float b) {
    __half2 p = __floats2half2_rn(a, b);
    return *(uint32_t*)&p;
}

// ---------------------------------------------------------------------------
// Weight conversion
// ---------------------------------------------------------------------------
__global__ void cvt_w(const float* __restrict__ x, __half* __restrict__ hi,
                      int n4) {
    int i = blockIdx.x * blockDim.x + threadIdx.x;
    if (i >= n4) return;
    float4 v = *(const float4*)(x + 4 * (size_t)i);
    __half2 p0 = __floats2half2_rn(v.x, v.y);
    __half2 p1 = __floats2half2_rn(v.z, v.w);
    *(__half2*)(hi + 4 * (size_t)i)     = p0;
    *(__half2*)(hi + 4 * (size_t)i + 2) = p1;
}

#define WP_N4 ((CC * CC) / 4)
#define W1_N4 ((HID * CC) / 4)
#define W2_N4 ((CC * HID) / 4)
#define CVT3_TOTAL (WP_N4 + W1_N4 + W2_N4)

__global__ void cvt3_w(const float* __restrict__ wp_f,
                       const float* __restrict__ w1_f,
                       const float* __restrict__ w2_f,
                       __half* __restrict__ wp_h,
                       __half* __restrict__ w1_h,
                       __half* __restrict__ w2_h) {
    int i = blockIdx.x * blockDim.x + threadIdx.x;
    if (i >= CVT3_TOTAL) return;
    const float* src;
    __half* dst;
    int idx;
    if (i < WP_N4) {
        src = wp_f; dst = wp_h; idx = i;
    } else if (i < WP_N4 + W1_N4) {
        src = w1_f; dst = w1_h; idx = i - WP_N4;
    } else {
        src = w2_f; dst = w2_h; idx = i - WP_N4 - W1_N4;
    }
    float4 v = *(const float4*)(src + 4 * (size_t)idx);
    __half2 p0 = __floats2half2_rn(v.x, v.y);
    __half2 p1 = __floats2half2_rn(v.z, v.w);
    *(__half2*)(dst + 4 * (size_t)idx)     = p0;
    *(__half2*)(dst + 4 * (size_t)idx + 2) = p1;
}

// ---------------------------------------------------------------------------
// LayerNorm -> fp16.  One warp per row.
// ---------------------------------------------------------------------------
__global__ void ln_kernel(const float* __restrict__ x,
                          const float* __restrict__ w,
                          const float* __restrict__ b,
                          __half* __restrict__ ohi) {
    const int warp = threadIdx.x >> 5;
    const int lane = threadIdx.x & 31;
    const int row  = blockIdx.x * 8 + warp;
    const float* xr = x + (size_t)row * CC;

    float4 v[4];
    #pragma unroll
    for (int k = 0; k < 4; k++)
        v[k] = *(const float4*)(xr + (k * 32 + lane) * 4);

    float s = 0.f;
    #pragma unroll
    for (int k = 0; k < 4; k++) s += v[k].x + v[k].y + v[k].z + v[k].w;
    #pragma unroll
    for (int o = 16; o > 0; o >>= 1) s += __shfl_xor_sync(0xffffffffu, s, o);
    const float mean = s * (1.0f / CC);

    float s2 = 0.f;
    #pragma unroll
    for (int k = 0; k < 4; k++) {
        float d0 = v[k].x - mean, d1 = v[k].y - mean;
        float d2 = v[k].z - mean, d3 = v[k].w - mean;
        s2 += d0 * d0 + d1 * d1 + d2 * d2 + d3 * d3;
    }
    #pragma unroll
    for (int o = 16; o > 0; o >>= 1) s2 += __shfl_xor_sync(0xffffffffu, s2, o);
    const float inv = rsqrtf(s2 * (1.0f / CC) + 1e-5f);

    #pragma unroll
    for (int k = 0; k < 4; k++) {
        const int col = (k * 32 + lane) * 4;
        float4 wv = *(const float4*)(w + col);
        float4 bv = *(const float4*)(b + col);
        float y0 = (v[k].x - mean) * inv * wv.x + bv.x;
        float y1 = (v[k].y - mean) * inv * wv.y + bv.y;
        float y2 = (v[k].z - mean) * inv * wv.z + bv.z;
        float y3 = (v[k].w - mean) * inv * wv.w + bv.w;
        uint2 o;
        o.x = pack_h2(y0, y1);
        o.y = pack_h2(y2, y3);
        *(uint2*)(ohi + (size_t)row * CC + col) = o;
    }
}

// ---------------------------------------------------------------------------
// mma.sync 1-pass fp16 NT GEMM (128x128 CTA, 64x32 warp tiles, 3-stage).
// ---------------------------------------------------------------------------
#define GEMM_STAGE 32768
#define GEMM_SMEM_BYTES (3 * GEMM_STAGE)

__device__ __forceinline__ void load_chunk(
    const __half* __restrict__ A, const __half* __restrict__ B,
    int K, int m0, int n0, int kc, uint32_t sbuf, int tid) {
    #pragma unroll
    for (int j = 0; j < 8; j++) {
        const int linear = j * 256 + tid;
        const int arr = j >> 2;
        const int within = linear & 1023;
        const int r = within >> 3;
        const int c = within & 7;
        uint32_t sw = sw128((uint32_t)(r * 128 + c * 16));
        if (arr == 0) {
            CP16(sbuf + sw,
                 (const char*)(A + (size_t)(m0 + r) * K + (size_t)kc * 64 + c * 8));
        } else {
            CP16(sbuf + 16384 + sw,
                 (const char*)(B + (size_t)(n0 + r) * K + (size_t)kc * 64 + c * 8));
        }
    }
}

#define G_LOAD(KS, AF, BF) do {                                               \
    _Pragma("unroll")                                                         \
    for (int mi_ = 0; mi_ < 4; mi_++)                                         \
        ldsm4((AF)[mi_], aS + aoff[mi_] + ccol[KS]);                          \
    _Pragma("unroll")                                                         \
    for (int nj_ = 0; nj_ < 2; nj_++)                                         \
        ldsm4((BF)[nj_], bS + boff[nj_] + ccol[KS]);                          \
} while (0)

#define G_MMA(AF, BF) do {                                                    \
    _Pragma("unroll")                                                         \
    for (int mi_ = 0; mi_ < 4; mi_++) {                                       \
        _Pragma("unroll")                                                     \
        for (int nt_ = 0; nt_ < 4; nt_++) {                                   \
            const int nj_ = nt_ >> 1;                                         \
            const int p_  = nt_ & 1;                                          \
            mma16816(d[mi_][nt_], (AF)[mi_], (BF)[nj_][p_],                   \
                     (BF)[nj_][p_ + 2]);                                      \
        }                                                                     \
    }                                                                         \
} while (0)

template <int EPI>
__global__ __launch_bounds__(256, 2)
void gemm_tc(const __half* __restrict__ A,
             const __half* __restrict__ B,
             const float* __restrict__ bias,
             const float* __restrict__ res,
             float* __restrict__ outF,
             __half* __restrict__ outH,
             int M, int Nn, int K) {
    extern __shared__ char dsm[];
    const uint32_t bufs = smem_u32(dsm);

    const int tid  = threadIdx.x;
    const int wid  = tid >> 5;
    const int lane = tid & 31;

    const int m0 = blockIdx.y * 128;
    const int n0 = blockIdx.x * 128;
    const int NK = K >> 6;

    const int warp_m = (wid & 1) * 64;
    const int warp_n = (wid >> 1) * 32;

    const int lrow = lane & 7;
    const int sel  = lane >> 3;
    const int rofs = lrow + ((sel & 1) ? 8 : 0);
    const int kofs = (sel & 2) ? 8 : 0;

    const uint32_t rxor = (uint32_t)lrow << 4;
    uint32_t aoff[4], boff[2], ccol[4];
    #pragma unroll
    for (int mi = 0; mi < 4; mi++)
        aoff[mi] = (uint32_t)((warp_m + 16 * mi + rofs) * 128);
    #pragma unroll
    for (int nj = 0; nj < 2; nj++)
        boff[nj] = (uint32_t)((warp_n + 16 * nj + rofs) * 128);
    #pragma unroll
    for (int ks = 0; ks < 4; ks++)
        ccol[ks] = ((uint32_t)((ks * 16 + kofs) * 2)) ^ rxor;

    float d[4][4][4] = {};

    load_chunk(A, B, K, m0, n0, 0, bufs, tid);
    CP_COMMIT();
    load_chunk(A, B, K, m0, n0, 1, bufs + GEMM_STAGE, tid);
    CP_COMMIT();

    for (int kc = 0; kc < NK; kc++) {
        const uint32_t bufc = bufs + (kc % 3) * GEMM_STAGE;
        if (kc + 1 < NK) { CP_WAIT1(); } else { CP_WAIT0(); }
        __syncthreads();

        const uint32_t aS = bufc;
        const uint32_t bS = bufc + 16384;

        uint32_t af0[4][4], bf0[2][4], af1[4][4], bf1[2][4];
        G_LOAD(0, af0, bf0);
        G_LOAD(1, af1, bf1);
        G_MMA(af0, bf0);
        G_LOAD(2, af0, bf0);
        G_MMA(af1, bf1);
        G_LOAD(3, af1, bf1);
        G_MMA(af0, bf0);
        G_MMA(af1, bf1);

        if (kc + 2 < NK) {
            load_chunk(A, B, K, m0, n0, kc + 2,
                       bufs + ((kc + 2) % 3) * GEMM_STAGE, tid);
            CP_COMMIT();
        }
    }

    const int erow0 = m0 + warp_m + (lane >> 2);
    const int ecol0 = n0 + warp_n + (lane & 3) * 2;

    #pragma unroll
    for (int mi = 0; mi < 4; mi++) {
        #pragma unroll
        for (int nt = 0; nt < 4; nt++) {
            const int col = ecol0 + nt * 8;
            #pragma unroll
            for (int half = 0; half < 2; half++) {
                const int row = erow0 + mi * 16 + half * 8;
                float v0 = d[mi][nt][2 * half + 0];
                float v1 = d[mi][nt][2 * half + 1];
                const size_t ob = (size_t)row * Nn + col;
                if (EPI == 1) {
                    float2 rv = *(const float2*)(res + ob);
                    v0 += bias[col]     + rv.x;
                    v1 += bias[col + 1] + rv.y;
                    *(float2*)(outF + ob) = make_float2(v0, v1);
                } else if (EPI == 2) {
                    v0 += bias[col];
                    v1 += bias[col + 1];
                    float g0 = v0 * normcdff(v0);
                    float g1 = v1 * normcdff(v1);
                    *(__half2*)(outH + ob) = __floats2half2_rn(g0, g1);
                } else {
                    *(__half2*)(outH + ob) = __floats2half2_rn(v0, v1);
                }
            }
        }
    }
}

// ---------------------------------------------------------------------------
// Tensor-core flash attention (per-batch pointers, q-range via qbase).
// grid = (q_tiles, HH).
// ---------------------------------------------------------------------------
#define AT_Q      0
#define AT_STAGE  16384
#define AT_BIAS   (16384 + 3 * 16384)
#define AT_SMEM_BYTES (AT_BIAS + 3 * 1024)

__device__ __forceinline__ void attn_prefetch(
    const __half* __restrict__ qv, const float* __restrict__ rpb,
    int h, int q0, int k0, uint32_t sbase, int s, int tid) {
    const uint32_t stage = sbase + AT_STAGE + s * 16384;
    #pragma unroll
    for (int j = 0; j < 4; j++) {
        int linear = tid + j * 256;
        int arr = linear >> 9;
        int within = linear & 511;
        int row = within >> 3;
        int c = within & 7;
        uint32_t dst = stage + arr * 8192 + sw128((uint32_t)(row * 128 + c * 16));
        int colbase = arr ? (2 * CC) : CC;
        CP16(dst, (const char*)(qv + (size_t)(k0 + row) * C3
                                + colbase + h * DH + c * 8));
    }
    if (tid < 192) {
        int idx = k0 - q0 + 1920 + tid;
        if (tid >= 191) idx = k0 - q0 + 1920;
        CP4(sbase + AT_BIAS + s * 1024 + tid * 4, rpb + (size_t)idx * HH + h);
    }
}

__global__ __launch_bounds__(256, 2)
void attn_tc(const __half* __restrict__ qv,
             const float* __restrict__ rpb,
             __half* __restrict__ outH,
             int qbase) {
    extern __shared__ char dsm[];
    const uint32_t sbase = smem_u32(dsm);

    const int q0 = qbase + blockIdx.x * 128;
    const int h = blockIdx.y;

    const int tid  = threadIdx.x;
    const int wid  = tid >> 5;
    const int lane = tid & 31;

    const int lrow = lane & 7;
    const int sel  = lane >> 3;
    const int rofs = lrow + ((sel & 1) ? 8 : 0);
    const int kofs = (sel & 2) ? 8 : 0;

    const uint32_t rxor = (uint32_t)lrow << 4;
    uint32_t krow[4], ccol[4];
    #pragma unroll
    for (int np = 0; np < 4; np++)
        krow[np] = (uint32_t)((np * 16 + rofs) * 128);
    #pragma unroll
    for (int kc = 0; kc < 4; kc++)
        ccol[kc] = ((uint32_t)((kc * 16 + kofs) * 2)) ^ rxor;

    const int g  = lane >> 3;
    const int rr = lane & 7;
    uint32_t vrow[4], vcol[4];
    #pragma unroll
    for (int kc = 0; kc < 4; kc++)
        vrow[kc] = (uint32_t)((kc * 16 + (g & 1) * 8 + rr) * 128);
    #pragma unroll
    for (int dp = 0; dp < 4; dp++)
        vcol[dp] = ((uint32_t)(dp * 32 + (g >> 1) * 16)) ^ ((uint32_t)rr << 4);

    #pragma unroll
    for (int j = 0; j < 4; j++) {
        int linear = tid + j * 256;
        int row = linear >> 3;
        int c = linear & 7;
        uint32_t dst = sbase + AT_Q + sw128((uint32_t)(row * 128 + c * 16));
        CP16(dst, (const char*)(qv + (size_t)(q0 + row) * C3 + h * DH + c * 8));
    }
    attn_prefetch(qv, rpb, h, q0, 0, sbase, 0, tid);
    CP_COMMIT();
    attn_prefetch(qv, rpb, h, q0, 64, sbase, 1, tid);
    CP_COMMIT();

    uint32_t qf[4][4];
    float oacc[8][4] = {};
    float m0 = -CUDART_INF_F, m1 = -CUDART_INF_F;
    float l0 = 0.f, l1 = 0.f;

    const int NCHUNK = NN / 64;
    for (int c = 0; c < NCHUNK; c++) {
        const int s = c % 3;
        const uint32_t stage = sbase + AT_STAGE + s * 16384;
        const uint32_t bstage = sbase + AT_BIAS + s * 1024;
        if (c + 1 < NCHUNK) { CP_WAIT1(); } else { CP_WAIT0(); }
        __syncthreads();

        if (c == 0) {
            #pragma unroll
            for (int kc = 0; kc < 4; kc++)
                ldsm4(qf[kc], sbase + AT_Q
                      + (uint32_t)((wid * 16 + rofs) * 128) + ccol[kc]);
        }

        float sacc[8][4] = {};
        #pragma unroll
        for (int kc = 0; kc < 4; kc++) {
            uint32_t kfA[4], kfB[4];
            ldsm4(kfA, stage + krow[0] + ccol[kc]);
            ldsm4(kfB, stage + krow[1] + ccol[kc]);
            mma16816(sacc[0], qf[kc], kfA[0], kfA[2]);
            mma16816(sacc[1], qf[kc], kfA[1], kfA[3]);
            ldsm4(kfA, stage + krow[2] + ccol[kc]);
            mma16816(sacc[2], qf[kc], kfB[0], kfB[2]);
            mma16816(sacc[3], qf[kc], kfB[1], kfB[3]);
            ldsm4(kfB, stage + krow[3] + ccol[kc]);
            mma16816(sacc[4], qf[kc], kfA[0], kfA[2]);
            mma16816(sacc[5], qf[kc], kfA[1], kfA[3]);
            mma16816(sacc[6], qf[kc], kfB[0], kfB[2]);
            mma16816(sacc[7], qf[kc], kfB[1], kfB[3]);
        }

        const int r0 = wid * 16 + (lane >> 2);
        const int cb = (lane & 3) * 2;
        float mx0 = -CUDART_INF_F, mx1 = -CUDART_INF_F;
        #pragma unroll
        for (int nt = 0; nt < 8; nt++) {
            const int kk = nt * 8 + cb;
            float bv0, bv1, bv2, bv3;
            asm volatile("ld.shared.f32 %0, [%1];" : "=f"(bv0)
                         : "r"(bstage + (kk - r0 + 127) * 4));
            asm volatile("ld.shared.f32 %0, [%1];" : "=f"(bv1)
                         : "r"(bstage + (kk + 1 - r0 + 127) * 4));
            asm volatile("ld.shared.f32 %0, [%1];" : "=f"(bv2)
                         : "r"(bstage + (kk - (r0 + 8) + 127) * 4));
            asm volatile("ld.shared.f32 %0, [%1];" : "=f"(bv3)
                         : "r"(bstage + (kk + 1 - (r0 + 8) + 127) * 4));
            sacc[nt][0] = fmaf(sacc[nt][0], 0.125f, bv0);
            sacc[nt][1] = fmaf(sacc[nt][1], 0.125f, bv1);
            sacc[nt][2] = fmaf(sacc[nt][2], 0.125f, bv2);
            sacc[nt][3] = fmaf(sacc[nt][3], 0.125f, bv3);
            mx0 = fmaxf(mx0, fmaxf(sacc[nt][0], sacc[nt][1]));
            mx1 = fmaxf(mx1, fmaxf(sacc[nt][2], sacc[nt][3]));
        }
        mx0 = fmaxf(mx0, __shfl_xor_sync(0xffffffffu, mx0, 1));
        mx0 = fmaxf(mx0, __shfl_xor_sync(0xffffffffu, mx0, 2));
        mx1 = fmaxf(mx1, __shfl_xor_sync(0xffffffffu, mx1, 1));
        mx1 = fmaxf(mx1, __shfl_xor_sync(0xffffffffu, mx1, 2));
        const float mn0 = fmaxf(m0, mx0);
        const float mn1 = fmaxf(m1, mx1);
        const float fac0 = __expf(m0 - mn0);
        const float fac1 = __expf(m1 - mn1);
        float sum0 = 0.f, sum1 = 0.f;
        #pragma unroll
        for (int nt = 0; nt < 8; nt++) {
            sacc[nt][0] = __expf(sacc[nt][0] - mn0);
            sacc[nt][1] = __expf(sacc[nt][1] - mn0);
            sacc[nt][2] = __expf(sacc[nt][2] - mn1);
            sacc[nt][3] = __expf(sacc[nt][3] - mn1);
            sum0 += sacc[nt][0] + sacc[nt][1];
            sum1 += sacc[nt][2] + sacc[nt][3];
        }
        sum0 += __shfl_xor_sync(0xffffffffu, sum0, 1);
        sum0 += __shfl_xor_sync(0xffffffffu, sum0, 2);
        sum1 += __shfl_xor_sync(0xffffffffu, sum1, 1);
        sum1 += __shfl_xor_sync(0xffffffffu, sum1, 2);
        l0 = l0 * fac0 + sum0;
        l1 = l1 * fac1 + sum1;
        m0 = mn0;
        m1 = mn1;
        #pragma unroll
        for (int nt = 0; nt < 8; nt++) {
            oacc[nt][0] *= fac0;
            oacc[nt][1] *= fac0;
            oacc[nt][2] *= fac1;
            oacc[nt][3] *= fac1;
        }

        const uint32_t vbase = stage + 8192;
        #pragma unroll
        for (int kc = 0; kc < 4; kc++) {
            uint32_t pA[4];
            #pragma unroll
            for (int gg = 0; gg < 2; gg++) {
                const float* sv = sacc[2 * kc + gg];
                pA[2 * gg + 0] = pack_h2(sv[0], sv[1]);
                pA[2 * gg + 1] = pack_h2(sv[2], sv[3]);
            }
            uint32_t vfA[4], vfB[4];
            ldsm4t(vfA, vbase + vrow[kc] + vcol[0]);
            ldsm4t(vfB, vbase + vrow[kc] + vcol[1]);
            mma16816(oacc[0], pA, vfA[0], vfA[1]);
            mma16816(oacc[1], pA, vfA[2], vfA[3]);
            ldsm4t(vfA, vbase + vrow[kc] + vcol[2]);
            mma16816(oacc[2], pA, vfB[0], vfB[1]);
            mma16816(oacc[3], pA, vfB[2], vfB[3]);
            ldsm4t(vfB, vbase + vrow[kc] + vcol[3]);
            mma16816(oacc[4], pA, vfA[0], vfA[1]);
            mma16816(oacc[5], pA, vfA[2], vfA[3]);
            mma16816(oacc[6], pA, vfB[0], vfB[1]);
            mma16816(oacc[7], pA, vfB[2], vfB[3]);
        }

        if (c + 2 < NCHUNK) {
            attn_prefetch(qv, rpb, h, q0, (c + 2) * 64, sbase, (c + 2) % 3, tid);
            CP_COMMIT();
        }
    }

    const float il0 = 1.0f / l0;
    const float il1 = 1.0f / l1;
    const int row0 = q0 + wid * 16 + (lane >> 2);
    const int colb = h * DH + (lane & 3) * 2;
    #pragma unroll
    for (int nt = 0; nt < 8; nt++) {
        const int col = colb + nt * 8;
        *(__half2*)(outH + (size_t)row0 * CC + col) =
            __floats2half2_rn(oacc[nt][0] * il0, oacc[nt][1] * il0);
        *(__half2*)(outH + (size_t)(row0 + 8) * CC + col) =
            __floats2half2_rn(oacc[nt][2] * il1, oacc[nt][3] * il1);
    }
}

// ---------------------------------------------------------------------------
// Launcher — 8 half-batch pipelines multiplexed onto 4 compute streams
// (main + 3 side) + 1 cvt stream.  Same stream count as the passing R12.
// ---------------------------------------------------------------------------
extern "C" void kernel_launch(void* const* d_in, const int* in_sizes, int n_in,
                              void* d_out, int out_size) {
    const float* x      = (const float*)d_in[0];
    const float* qkv_w  = (const float*)d_in[1];
    const float* proj_w = (const float*)d_in[2];
    const float* proj_b = (const float*)d_in[3];
    const float* rpb    = (const float*)d_in[4];
    const float* n1_w   = (const float*)d_in[5];
    const float* n1_b   = (const float*)d_in[6];
    const float* n2_w   = (const float*)d_in[7];
    const float* n2_b   = (const float*)d_in[8];
    const float* fc1_w  = (const float*)d_in[9];
    const float* fc1_b  = (const float*)d_in[10];
    const float* fc2_w  = (const float*)d_in[11];
    const float* fc2_b  = (const float*)d_in[12];
    float* out = (float*)d_out;

    float *x1;
    __half *qv, *h1, *at, *h2, *hd, *wq, *wp, *w1, *w2;
    cudaGetSymbolAddress((void**)&x1, g_x1);
    cudaGetSymbolAddress((void**)&qv, g_qv);
    cudaGetSymbolAddress((void**)&h1, g_h1);
    cudaGetSymbolAddress((void**)&at, g_at);
    cudaGetSymbolAddress((void**)&h2, g_h2);
    cudaGetSymbolAddress((void**)&hd, g_hd);
    cudaGetSymbolAddress((void**)&wq, g_wq);
    cudaGetSymbolAddress((void**)&wp, g_wp);
    cudaGetSymbolAddress((void**)&w1, g_w1);
    cudaGetSymbolAddress((void**)&w2, g_w2);

    cudaFuncSetAttribute(gemm_tc<1>, cudaFuncAttributeMaxDynamicSharedMemorySize, GEMM_SMEM_BYTES);
    cudaFuncSetAttribute(gemm_tc<2>, cudaFuncAttributeMaxDynamicSharedMemorySize, GEMM_SMEM_BYTES);
    cudaFuncSetAttribute(gemm_tc<3>, cudaFuncAttributeMaxDynamicSharedMemorySize, GEMM_SMEM_BYTES);
    cudaFuncSetAttribute(attn_tc, cudaFuncAttributeMaxDynamicSharedMemorySize, AT_SMEM_BYTES);

    // Streams: main (0) + side[0..2] for compute; side[3] for conversions.
    cudaStream_t side[4];
    cudaEvent_t e_fork, e_wq, e_rest, e_q[8], e_done[3];
    for (int i = 0; i < 4; i++)
        cudaStreamCreateWithFlags(&side[i], cudaStreamNonBlocking);
    cudaEventCreateWithFlags(&e_fork, cudaEventDisableTiming);
    cudaEventCreateWithFlags(&e_wq,   cudaEventDisableTiming);
    cudaEventCreateWithFlags(&e_rest, cudaEventDisableTiming);
    for (int i = 0; i < 8; i++)
        cudaEventCreateWithFlags(&e_q[i], cudaEventDisableTiming);
    for (int i = 0; i < 3; i++)
        cudaEventCreateWithFlags(&e_done[i], cudaEventDisableTiming);

    // Fork
    cudaEventRecord(e_fork, 0);
    for (int i = 0; i < 4; i++) cudaStreamWaitEvent(side[i], e_fork, 0);

    // Weight conversions on side[3]
    cvt_w<<<(C3 * CC) / 1024, 256, 0, side[3]>>>(qkv_w, wq, (C3 * CC) / 4);
    cudaEventRecord(e_wq, side[3]);
    cvt3_w<<<(CVT3_TOTAL + 255) / 256, 256, 0, side[3]>>>(proj_w, fc1_w, fc2_w,
                                                          wp, w1, w2);
    cudaEventRecord(e_rest, side[3]);

    // chunk ch -> stream ch & 3 (main for 0, side[s-1] otherwise)
    #define CH_STREAM(ch) (((ch) & 3) == 0 ? (cudaStream_t)0 : side[((ch) & 3) - 1])

    // Phase 1: ln1 + qkv per half-chunk
    for (int ch = 0; ch < 8; ch++) {
        cudaStream_t st = CH_STREAM(ch);
        const size_t rb = (size_t)ch * MB2;

        ln_kernel<<<MB2 / 8, 256, 0, st>>>(x + rb * CC, n1_w, n1_b,
                                           h1 + rb * CC);
        cudaStreamWaitEvent(st, e_wq, 0);
        gemm_tc<3><<<dim3(C3 / 128, MB2 / 128), 256, GEMM_SMEM_BYTES, st>>>(
            h1 + rb * CC, wq, nullptr, nullptr, nullptr, qv + rb * C3,
            MB2, C3, CC);
        cudaEventRecord(e_q[ch], st);
    }

    // Phase 2: attention (waits on sibling half's qkv) + proj/ln2/fc1/fc2
    for (int ch = 0; ch < 8; ch++) {
        cudaStream_t st = CH_STREAM(ch);
        const int b = ch >> 1;
        const int half = ch & 1;
        const int sib = b * 2 + (half ^ 1);
        const size_t rb = (size_t)ch * MB2;
        const size_t bb = (size_t)b * NN;

        cudaStreamWaitEvent(st, e_q[sib], 0);
        attn_tc<<<dim3(MB2 / 128, HH), 256, AT_SMEM_BYTES, st>>>(
            qv + bb * C3, rpb, at + bb * CC, half * MB2);

        cudaStreamWaitEvent(st, e_rest, 0);
        gemm_tc<1><<<dim3(CC / 128, MB2 / 128), 256, GEMM_SMEM_BYTES, st>>>(
            at + rb * CC, wp, proj_b, x + rb * CC, x1 + rb * CC, nullptr,
            MB2, CC, CC);

        ln_kernel<<<MB2 / 8, 256, 0, st>>>(x1 + rb * CC, n2_w, n2_b,
                                           h2 + rb * CC);

        gemm_tc<2><<<dim3(HID / 128, MB2 / 128), 256, GEMM_SMEM_BYTES, st>>>(
            h2 + rb * CC, w1, fc1_b, nullptr, nullptr, hd + rb * HID,
            MB2, HID, CC);

        gemm_tc<1><<<dim3(CC / 128, MB2 / 128), 256, GEMM_SMEM_BYTES, st>>>(
            hd + rb * HID, w2, fc2_b, x1 + rb * CC, out + rb * CC, nullptr,
            MB2, CC, HID);

        if ((ch & 3) != 0 && ch >= 4) cudaEventRecord(e_done[(ch & 3) - 1], st);
    }

    // Join side compute streams back into the main stream.
    for (int i = 0; i < 3; i++) cudaStreamWaitEvent(0, e_done[i], 0);

    cudaEventDestroy(e_fork);
    cudaEventDestroy(e_wq);
    cudaEventDestroy(e_rest);
    for (int i = 0; i < 8; i++) cudaEventDestroy(e_q[i]);
    for (int i = 0; i < 3; i++) cudaEventDestroy(e_done[i]);
    for (int i = 0; i < 4; i++) cudaStreamDestroy(side[i]);
}

// round 15
// speedup vs baseline: 1.1883x; 1.1883x over previous
#include <cuda_runtime.h>
#include <cuda_fp16.h>
#include <math.h>
#include <math_constants.h>
#include <stdint.h>

// Problem constants
#define BB    4
#define NN    2048
#define CC    512
#define HH    8
#define DH    64
#define HID   2048
#define MROWS (BB * NN)   // 8192
#define C3    (3 * CC)    // 1536
#define MB    NN          // rows per batch chunk (2048)

// ---------------------------------------------------------------------------
// Device scratch
// ---------------------------------------------------------------------------
__device__ float g_x1 [MROWS * CC];

__device__ __half g_qv[MROWS * C3];
__device__ __half g_h1[MROWS * CC];
__device__ __half g_at[MROWS * CC];
__device__ __half g_h2[MROWS * CC];
__device__ __half g_hd[MROWS * HID];

__device__ __half g_wq[C3 * CC];
__device__ __half g_wp[CC * CC];
__device__ __half g_w1[HID * CC];
__device__ __half g_w2[CC * HID];

// ---------------------------------------------------------------------------
// PTX helpers
// ---------------------------------------------------------------------------
__device__ __forceinline__ uint32_t smem_u32(const void* p) {
    uint32_t a;
    asm("{ .reg .u64 t; cvta.to.shared.u64 t, %1; cvt.u32.u64 %0, t; }"
        : "=r"(a) : "l"(p));
    return a;
}

#define CP16(dst, src)                                                        \
    asm volatile("cp.async.cg.shared.global [%0], [%1], 16;"                  \
                 :: "r"(dst), "l"(src))
#define CP4(dst, src)                                                         \
    asm volatile("cp.async.ca.shared.global [%0], [%1], 4;"                   \
                 :: "r"(dst), "l"(src))
#define CP_COMMIT() asm volatile("cp.async.commit_group;" ::: "memory")
#define CP_WAIT1()  asm volatile("cp.async.wait_group 1;" ::: "memory")
#define CP_WAIT0()  asm volatile("cp.async.wait_group 0;" ::: "memory")

__device__ __forceinline__ void ldsm4(uint32_t* r, uint32_t addr) {
    asm volatile("ldmatrix.sync.aligned.m8n8.x4.shared.b16 {%0,%1,%2,%3}, [%4];"
                 : "=r"(r[0]), "=r"(r[1]), "=r"(r[2]), "=r"(r[3]) : "r"(addr));
}

__device__ __forceinline__ void ldsm4t(uint32_t* r, uint32_t addr) {
    asm volatile("ldmatrix.sync.aligned.m8n8.x4.trans.shared.b16 {%0,%1,%2,%3}, [%4];"
                 : "=r"(r[0]), "=r"(r[1]), "=r"(r[2]), "=r"(r[3]) : "r"(addr));
}

__device__ __forceinline__ void mma16816(float* d, const uint32_t* a,
                                         uint32_t b0, uint32_t b1) {
    asm volatile(
        "mma.sync.aligned.m16n8k16.row.col.f32.f16.f16.f32 "
        "{%0,%1,%2,%3}, {%4,%5,%6,%7}, {%8,%9}, {%0,%1,%2,%3};"
        : "+f"(d[0]), "+f"(d[1]), "+f"(d[2]), "+f"(d[3])
        : "r"(a[0]), "r"(a[1]), "r"(a[2]), "r"(a[3]), "r"(b0), "r"(b1));
}

__device__ __forceinline__ uint32_t sw128(uint32_t off) {
    return off ^ ((off >> 3) & 0x70u);
}

__device__ __forceinline__ uint32_t pack_h2(float a, float b) {
    __half2 p = __floats2half2_rn(a, b);
    return *(uint32_t*)&p;
}

// ---------------------------------------------------------------------------
// Weight conversion
// ---------------------------------------------------------------------------
__global__ void cvt_w(const float* __restrict__ x, __half* __restrict__ hi,
                      int n4) {
    int i = blockIdx.x * blockDim.x + threadIdx.x;
    if (i >= n4) return;
    float4 v = *(const float4*)(x + 4 * (size_t)i);
    __half2 p0 = __floats2half2_rn(v.x, v.y);
    __half2 p1 = __floats2half2_rn(v.z, v.w);
    *(__half2*)(hi + 4 * (size_t)i)     = p0;
    *(__half2*)(hi + 4 * (size_t)i + 2) = p1;
}

#define WP_N4 ((CC * CC) / 4)
#define W1_N4 ((HID * CC) / 4)
#define W2_N4 ((CC * HID) / 4)
#define CVT3_TOTAL (WP_N4 + W1_N4 + W2_N4)

__global__ void cvt3_w(const float* __restrict__ wp_f,
                       const float* __restrict__ w1_f,
                       const float* __restrict__ w2_f,
                       __half* __restrict__ wp_h,
                       __half* __restrict__ w1_h,
                       __half* __restrict__ w2_h) {
    int i = blockIdx.x * blockDim.x + threadIdx.x;
    if (i >= CVT3_TOTAL) return;
    const float* src;
    __half* dst;
    int idx;
    if (i < WP_N4) {
        src = wp_f; dst = wp_h; idx = i;
    } else if (i < WP_N4 + W1_N4) {
        src = w1_f; dst = w1_h; idx = i - WP_N4;
    } else {
        src = w2_f; dst = w2_h; idx = i - WP_N4 - W1_N4;
    }
    float4 v = *(const float4*)(src + 4 * (size_t)idx);
    __half2 p0 = __floats2half2_rn(v.x, v.y);
    __half2 p1 = __floats2half2_rn(v.z, v.w);
    *(__half2*)(dst + 4 * (size_t)idx)     = p0;
    *(__half2*)(dst + 4 * (size_t)idx + 2) = p1;
}

// ---------------------------------------------------------------------------
// LayerNorm -> fp16.  One warp per row.
// ---------------------------------------------------------------------------
__global__ void ln_kernel(const float* __restrict__ x,
                          const float* __restrict__ w,
                          const float* __restrict__ b,
                          __half* __restrict__ ohi) {
    const int warp = threadIdx.x >> 5;
    const int lane = threadIdx.x & 31;
    const int row  = blockIdx.x * 8 + warp;
    const float* xr = x + (size_t)row * CC;

    float4 v[4];
    #pragma unroll
    for (int k = 0; k < 4; k++)
        v[k] = *(const float4*)(xr + (k * 32 + lane) * 4);

    float s = 0.f;
    #pragma unroll
    for (int k = 0; k < 4; k++) s += v[k].x + v[k].y + v[k].z + v[k].w;
    #pragma unroll
    for (int o = 16; o > 0; o >>= 1) s += __shfl_xor_sync(0xffffffffu, s, o);
    const float mean = s * (1.0f / CC);

    float s2 = 0.f;
    #pragma unroll
    for (int k = 0; k < 4; k++) {
        float d0 = v[k].x - mean, d1 = v[k].y - mean;
        float d2 = v[k].z - mean, d3 = v[k].w - mean;
        s2 += d0 * d0 + d1 * d1 + d2 * d2 + d3 * d3;
    }
    #pragma unroll
    for (int o = 16; o > 0; o >>= 1) s2 += __shfl_xor_sync(0xffffffffu, s2, o);
    const float inv = rsqrtf(s2 * (1.0f / CC) + 1e-5f);

    #pragma unroll
    for (int k = 0; k < 4; k++) {
        const int col = (k * 32 + lane) * 4;
        float4 wv = *(const float4*)(w + col);
        float4 bv = *(const float4*)(b + col);
        float y0 = (v[k].x - mean) * inv * wv.x + bv.x;
        float y1 = (v[k].y - mean) * inv * wv.y + bv.y;
        float y2 = (v[k].z - mean) * inv * wv.z + bv.z;
        float y3 = (v[k].w - mean) * inv * wv.w + bv.w;
        uint2 o;
        o.x = pack_h2(y0, y1);
        o.y = pack_h2(y2, y3);
        *(uint2*)(ohi + (size_t)row * CC + col) = o;
    }
}

// ---------------------------------------------------------------------------
// mma.sync 1-pass fp16 NT GEMM.
// CTA tile 128x64, warp tile 32x32 (4x2 warp grid), BK=64, 3-stage cp.async.
// Smaller accumulator footprint -> ~84 regs -> 3 CTAs/SM (24 warps).
// SMEM stage: [A 16K][B 8K] = 24K.
// ---------------------------------------------------------------------------
#define GEMM_STAGE 24576
#define GEMM_SMEM_BYTES (3 * GEMM_STAGE)

__device__ __forceinline__ void load_chunk(
    const __half* __restrict__ A, const __half* __restrict__ B,
    int K, int m0, int n0, int kc, uint32_t sbuf, int tid) {
    // A: 128 rows x 8 chunks = 1024 (j 0..3);  B: 64 x 8 = 512 (j 4..5)
    #pragma unroll
    for (int j = 0; j < 6; j++) {
        const int linear = j * 256 + tid;
        if (j < 4) {
            const int r = linear >> 3;
            const int c = linear & 7;
            uint32_t sw = sw128((uint32_t)(r * 128 + c * 16));
            CP16(sbuf + sw,
                 (const char*)(A + (size_t)(m0 + r) * K + (size_t)kc * 64 + c * 8));
        } else {
            const int idx = linear - 1024;
            const int r = idx >> 3;
            const int c = idx & 7;
            uint32_t sw = sw128((uint32_t)(r * 128 + c * 16));
            CP16(sbuf + 16384 + sw,
                 (const char*)(B + (size_t)(n0 + r) * K + (size_t)kc * 64 + c * 8));
        }
    }
}

template <int EPI>
__global__ __launch_bounds__(256, 3)
void gemm_tc(const __half* __restrict__ A,
             const __half* __restrict__ B,
             const float* __restrict__ bias,
             const float* __restrict__ res,
             float* __restrict__ outF,
             __half* __restrict__ outH,
             int M, int Nn, int K) {
    extern __shared__ char dsm[];
    const uint32_t bufs = smem_u32(dsm);

    const int tid  = threadIdx.x;
    const int wid  = tid >> 5;
    const int lane = tid & 31;

    const int m0 = blockIdx.y * 128;
    const int n0 = blockIdx.x * 64;
    const int NK = K >> 6;

    const int warp_m = (wid & 3) * 32;
    const int warp_n = (wid >> 2) * 32;

    const int lrow = lane & 7;
    const int sel  = lane >> 3;
    const int rofs = lrow + ((sel & 1) ? 8 : 0);
    const int kofs = (sel & 2) ? 8 : 0;

    const uint32_t rxor = (uint32_t)lrow << 4;
    uint32_t aoff[2], boff[2], ccol[4];
    #pragma unroll
    for (int mi = 0; mi < 2; mi++)
        aoff[mi] = (uint32_t)((warp_m + 16 * mi + rofs) * 128);
    #pragma unroll
    for (int nj = 0; nj < 2; nj++)
        boff[nj] = (uint32_t)((warp_n + 16 * nj + rofs) * 128);
    #pragma unroll
    for (int ks = 0; ks < 4; ks++)
        ccol[ks] = ((uint32_t)((ks * 16 + kofs) * 2)) ^ rxor;

    float d[2][4][4] = {};

    load_chunk(A, B, K, m0, n0, 0, bufs, tid);
    CP_COMMIT();
    load_chunk(A, B, K, m0, n0, 1, bufs + GEMM_STAGE, tid);
    CP_COMMIT();

    for (int kc = 0; kc < NK; kc++) {
        const uint32_t bufc = bufs + (kc % 3) * GEMM_STAGE;
        if (kc + 1 < NK) { CP_WAIT1(); } else { CP_WAIT0(); }
        __syncthreads();

        const uint32_t aS = bufc;
        const uint32_t bS = bufc + 16384;

        #pragma unroll
        for (int ks = 0; ks < 4; ks++) {
            uint32_t af[2][4], bf[2][4];
            #pragma unroll
            for (int mi = 0; mi < 2; mi++)
                ldsm4(af[mi], aS + aoff[mi] + ccol[ks]);
            #pragma unroll
            for (int nj = 0; nj < 2; nj++)
                ldsm4(bf[nj], bS + boff[nj] + ccol[ks]);
            #pragma unroll
            for (int mi = 0; mi < 2; mi++) {
                #pragma unroll
                for (int nt = 0; nt < 4; nt++) {
                    const int nj = nt >> 1;
                    const int p  = nt & 1;
                    mma16816(d[mi][nt], af[mi], bf[nj][p], bf[nj][p + 2]);
                }
            }
        }

        if (kc + 2 < NK) {
            load_chunk(A, B, K, m0, n0, kc + 2,
                       bufs + ((kc + 2) % 3) * GEMM_STAGE, tid);
            CP_COMMIT();
        }
    }

    const int erow0 = m0 + warp_m + (lane >> 2);
    const int ecol0 = n0 + warp_n + (lane & 3) * 2;

    #pragma unroll
    for (int mi = 0; mi < 2; mi++) {
        #pragma unroll
        for (int nt = 0; nt < 4; nt++) {
            const int col = ecol0 + nt * 8;
            #pragma unroll
            for (int half = 0; half < 2; half++) {
                const int row = erow0 + mi * 16 + half * 8;
                float v0 = d[mi][nt][2 * half + 0];
                float v1 = d[mi][nt][2 * half + 1];
                const size_t ob = (size_t)row * Nn + col;
                if (EPI == 1) {
                    float2 rv = *(const float2*)(res + ob);
                    v0 += bias[col]     + rv.x;
                    v1 += bias[col + 1] + rv.y;
                    *(float2*)(outF + ob) = make_float2(v0, v1);
                } else if (EPI == 2) {
                    v0 += bias[col];
                    v1 += bias[col + 1];
                    float g0 = v0 * normcdff(v0);
                    float g1 = v1 * normcdff(v1);
                    *(__half2*)(outH + ob) = __floats2half2_rn(g0, g1);
                } else {
                    *(__half2*)(outH + ob) = __floats2half2_rn(v0, v1);
                }
            }
        }
    }
}

// ---------------------------------------------------------------------------
// Tensor-core flash attention (R12 version, per-batch launch).
// ---------------------------------------------------------------------------
#define AT_Q      0
#define AT_STAGE  16384
#define AT_BIAS   (16384 + 3 * 16384)
#define AT_SMEM_BYTES (AT_BIAS + 3 * 1024)

__device__ __forceinline__ void attn_prefetch(
    const __half* __restrict__ qv, const float* __restrict__ rpb,
    int h, int q0, int k0, uint32_t sbase, int s, int tid) {
    const uint32_t stage = sbase + AT_STAGE + s * 16384;
    #pragma unroll
    for (int j = 0; j < 4; j++) {
        int linear = tid + j * 256;
        int arr = linear >> 9;
        int within = linear & 511;
        int row = within >> 3;
        int c = within & 7;
        uint32_t dst = stage + arr * 8192 + sw128((uint32_t)(row * 128 + c * 16));
        int colbase = arr ? (2 * CC) : CC;
        CP16(dst, (const char*)(qv + (size_t)(k0 + row) * C3
                                + colbase + h * DH + c * 8));
    }
    if (tid < 192) {
        int idx = k0 - q0 + 1920 + tid;
        if (tid >= 191) idx = k0 - q0 + 1920;
        CP4(sbase + AT_BIAS + s * 1024 + tid * 4, rpb + (size_t)idx * HH + h);
    }
}

__global__ __launch_bounds__(256, 2)
void attn_tc(const __half* __restrict__ qv,
             const float* __restrict__ rpb,
             __half* __restrict__ outH) {
    extern __shared__ char dsm[];
    const uint32_t sbase = smem_u32(dsm);

    const int q0 = blockIdx.x * 128;
    const int h = blockIdx.y;

    const int tid  = threadIdx.x;
    const int wid  = tid >> 5;
    const int lane = tid & 31;

    const int lrow = lane & 7;
    const int sel  = lane >> 3;
    const int rofs = lrow + ((sel & 1) ? 8 : 0);
    const int kofs = (sel & 2) ? 8 : 0;

    const uint32_t rxor = (uint32_t)lrow << 4;
    uint32_t krow[4], ccol[4];
    #pragma unroll
    for (int np = 0; np < 4; np++)
        krow[np] = (uint32_t)((np * 16 + rofs) * 128);
    #pragma unroll
    for (int kc = 0; kc < 4; kc++)
        ccol[kc] = ((uint32_t)((kc * 16 + kofs) * 2)) ^ rxor;

    const int g  = lane >> 3;
    const int rr = lane & 7;
    uint32_t vrow[4], vcol[4];
    #pragma unroll
    for (int kc = 0; kc < 4; kc++)
        vrow[kc] = (uint32_t)((kc * 16 + (g & 1) * 8 + rr) * 128);
    #pragma unroll
    for (int dp = 0; dp < 4; dp++)
        vcol[dp] = ((uint32_t)(dp * 32 + (g >> 1) * 16)) ^ ((uint32_t)rr << 4);

    #pragma unroll
    for (int j = 0; j < 4; j++) {
        int linear = tid + j * 256;
        int row = linear >> 3;
        int c = linear & 7;
        uint32_t dst = sbase + AT_Q + sw128((uint32_t)(row * 128 + c * 16));
        CP16(dst, (const char*)(qv + (size_t)(q0 + row) * C3 + h * DH + c * 8));
    }
    attn_prefetch(qv, rpb, h, q0, 0, sbase, 0, tid);
    CP_COMMIT();
    attn_prefetch(qv, rpb, h, q0, 64, sbase, 1, tid);
    CP_COMMIT();

    uint32_t qf[4][4];
    float oacc[8][4] = {};
    float m0 = -CUDART_INF_F, m1 = -CUDART_INF_F;
    float l0 = 0.f, l1 = 0.f;

    const int NCHUNK = NN / 64;
    for (int c = 0; c < NCHUNK; c++) {
        const int s = c % 3;
        const uint32_t stage = sbase + AT_STAGE + s * 16384;
        const uint32_t bstage = sbase + AT_BIAS + s * 1024;
        if (c + 1 < NCHUNK) { CP_WAIT1(); } else { CP_WAIT0(); }
        __syncthreads();

        if (c == 0) {
            #pragma unroll
            for (int kc = 0; kc < 4; kc++)
                ldsm4(qf[kc], sbase + AT_Q
                      + (uint32_t)((wid * 16 + rofs) * 128) + ccol[kc]);
        }

        float sacc[8][4] = {};
        #pragma unroll
        for (int kc = 0; kc < 4; kc++) {
            uint32_t kfA[4], kfB[4];
            ldsm4(kfA, stage + krow[0] + ccol[kc]);
            ldsm4(kfB, stage + krow[1] + ccol[kc]);
            mma16816(sacc[0], qf[kc], kfA[0], kfA[2]);
            mma16816(sacc[1], qf[kc], kfA[1], kfA[3]);
            ldsm4(kfA, stage + krow[2] + ccol[kc]);
            mma16816(sacc[2], qf[kc], kfB[0], kfB[2]);
            mma16816(sacc[3], qf[kc], kfB[1], kfB[3]);
            ldsm4(kfB, stage + krow[3] + ccol[kc]);
            mma16816(sacc[4], qf[kc], kfA[0], kfA[2]);
            mma16816(sacc[5], qf[kc], kfA[1], kfA[3]);
            mma16816(sacc[6], qf[kc], kfB[0], kfB[2]);
            mma16816(sacc[7], qf[kc], kfB[1], kfB[3]);
        }

        const int r0 = wid * 16 + (lane >> 2);
        const int cb = (lane & 3) * 2;
        float mx0 = -CUDART_INF_F, mx1 = -CUDART_INF_F;
        #pragma unroll
        for (int nt = 0; nt < 8; nt++) {
            const int kk = nt * 8 + cb;
            float bv0, bv1, bv2, bv3;
            asm volatile("ld.shared.f32 %0, [%1];" : "=f"(bv0)
                         : "r"(bstage + (kk - r0 + 127) * 4));
            asm volatile("ld.shared.f32 %0, [%1];" : "=f"(bv1)
                         : "r"(bstage + (kk + 1 - r0 + 127) * 4));
            asm volatile("ld.shared.f32 %0, [%1];" : "=f"(bv2)
                         : "r"(bstage + (kk - (r0 + 8) + 127) * 4));
            asm volatile("ld.shared.f32 %0, [%1];" : "=f"(bv3)
                         : "r"(bstage + (kk + 1 - (r0 + 8) + 127) * 4));
            sacc[nt][0] = fmaf(sacc[nt][0], 0.125f, bv0);
            sacc[nt][1] = fmaf(sacc[nt][1], 0.125f, bv1);
            sacc[nt][2] = fmaf(sacc[nt][2], 0.125f, bv2);
            sacc[nt][3] = fmaf(sacc[nt][3], 0.125f, bv3);
            mx0 = fmaxf(mx0, fmaxf(sacc[nt][0], sacc[nt][1]));
            mx1 = fmaxf(mx1, fmaxf(sacc[nt][2], sacc[nt][3]));
        }
        mx0 = fmaxf(mx0, __shfl_xor_sync(0xffffffffu, mx0, 1));
        mx0 = fmaxf(mx0, __shfl_xor_sync(0xffffffffu, mx0, 2));
        mx1 = fmaxf(mx1, __shfl_xor_sync(0xffffffffu, mx1, 1));
        mx1 = fmaxf(mx1, __shfl_xor_sync(0xffffffffu, mx1, 2));
        const float mn0 = fmaxf(m0, mx0);
        const float mn1 = fmaxf(m1, mx1);
        const float fac0 = __expf(m0 - mn0);
        const float fac1 = __expf(m1 - mn1);
        float sum0 = 0.f, sum1 = 0.f;
        #pragma unroll
        for (int nt = 0; nt < 8; nt++) {
            sacc[nt][0] = __expf(sacc[nt][0] - mn0);
            sacc[nt][1] = __expf(sacc[nt][1] - mn0);
            sacc[nt][2] = __expf(sacc[nt][2] - mn1);
            sacc[nt][3] = __expf(sacc[nt][3] - mn1);
            sum0 += sacc[nt][0] + sacc[nt][1];
            sum1 += sacc[nt][2] + sacc[nt][3];
        }
        sum0 += __shfl_xor_sync(0xffffffffu, sum0, 1);
        sum0 += __shfl_xor_sync(0xffffffffu, sum0, 2);
        sum1 += __shfl_xor_sync(0xffffffffu, sum1, 1);
        sum1 += __shfl_xor_sync(0xffffffffu, sum1, 2);
        l0 = l0 * fac0 + sum0;
        l1 = l1 * fac1 + sum1;
        m0 = mn0;
        m1 = mn1;
        #pragma unroll
        for (int nt = 0; nt < 8; nt++) {
            oacc[nt][0] *= fac0;
            oacc[nt][1] *= fac0;
            oacc[nt][2] *= fac1;
            oacc[nt][3] *= fac1;
        }

        const uint32_t vbase = stage + 8192;
        #pragma unroll
        for (int kc = 0; kc < 4; kc++) {
            uint32_t pA[4];
            #pragma unroll
            for (int gg = 0; gg < 2; gg++) {
                const float* sv = sacc[2 * kc + gg];
                pA[2 * gg + 0] = pack_h2(sv[0], sv[1]);
                pA[2 * gg + 1] = pack_h2(sv[2], sv[3]);
            }
            uint32_t vfA[4], vfB[4];
            ldsm4t(vfA, vbase + vrow[kc] + vcol[0]);
            ldsm4t(vfB, vbase + vrow[kc] + vcol[1]);
            mma16816(oacc[0], pA, vfA[0], vfA[1]);
            mma16816(oacc[1], pA, vfA[2], vfA[3]);
            ldsm4t(vfA, vbase + vrow[kc] + vcol[2]);
            mma16816(oacc[2], pA, vfB[0], vfB[1]);
            mma16816(oacc[3], pA, vfB[2], vfB[3]);
            ldsm4t(vfB, vbase + vrow[kc] + vcol[3]);
            mma16816(oacc[4], pA, vfA[0], vfA[1]);
            mma16816(oacc[5], pA, vfA[2], vfA[3]);
            mma16816(oacc[6], pA, vfB[0], vfB[1]);
            mma16816(oacc[7], pA, vfB[2], vfB[3]);
        }

        if (c + 2 < NCHUNK) {
            attn_prefetch(qv, rpb, h, q0, (c + 2) * 64, sbase, (c + 2) % 3, tid);
            CP_COMMIT();
        }
    }

    const float il0 = 1.0f / l0;
    const float il1 = 1.0f / l1;
    const int row0 = q0 + wid * 16 + (lane >> 2);
    const int colb = h * DH + (lane & 3) * 2;
    #pragma unroll
    for (int nt = 0; nt < 8; nt++) {
        const int col = colb + nt * 8;
        *(__half2*)(outH + (size_t)row0 * CC + col) =
            __floats2half2_rn(oacc[nt][0] * il0, oacc[nt][1] * il0);
        *(__half2*)(outH + (size_t)(row0 + 8) * CC + col) =
            __floats2half2_rn(oacc[nt][2] * il1, oacc[nt][3] * il1);
    }
}

// ---------------------------------------------------------------------------
// Launcher — 4 per-batch pipelines (R12 structure).
// ---------------------------------------------------------------------------
extern "C" void kernel_launch(void* const* d_in, const int* in_sizes, int n_in,
                              void* d_out, int out_size) {
    const float* x      = (const float*)d_in[0];
    const float* qkv_w  = (const float*)d_in[1];
    const float* proj_w = (const float*)d_in[2];
    const float* proj_b = (const float*)d_in[3];
    const float* rpb    = (const float*)d_in[4];
    const float* n1_w   = (const float*)d_in[5];
    const float* n1_b   = (const float*)d_in[6];
    const float* n2_w   = (const float*)d_in[7];
    const float* n2_b   = (const float*)d_in[8];
    const float* fc1_w  = (const float*)d_in[9];
    const float* fc1_b  = (const float*)d_in[10];
    const float* fc2_w  = (const float*)d_in[11];
    const float* fc2_b  = (const float*)d_in[12];
    float* out = (float*)d_out;

    float *x1;
    __half *qv, *h1, *at, *h2, *hd, *wq, *wp, *w1, *w2;
    cudaGetSymbolAddress((void**)&x1, g_x1);
    cudaGetSymbolAddress((void**)&qv, g_qv);
    cudaGetSymbolAddress((void**)&h1, g_h1);
    cudaGetSymbolAddress((void**)&at, g_at);
    cudaGetSymbolAddress((void**)&h2, g_h2);
    cudaGetSymbolAddress((void**)&hd, g_hd);
    cudaGetSymbolAddress((void**)&wq, g_wq);
    cudaGetSymbolAddress((void**)&wp, g_wp);
    cudaGetSymbolAddress((void**)&w1, g_w1);
    cudaGetSymbolAddress((void**)&w2, g_w2);

    cudaFuncSetAttribute(gemm_tc<1>, cudaFuncAttributeMaxDynamicSharedMemorySize, GEMM_SMEM_BYTES);
    cudaFuncSetAttribute(gemm_tc<2>, cudaFuncAttributeMaxDynamicSharedMemorySize, GEMM_SMEM_BYTES);
    cudaFuncSetAttribute(gemm_tc<3>, cudaFuncAttributeMaxDynamicSharedMemorySize, GEMM_SMEM_BYTES);
    cudaFuncSetAttribute(attn_tc, cudaFuncAttributeMaxDynamicSharedMemorySize, AT_SMEM_BYTES);

    // Streams: main (0) runs batch 0; side[0..2] run batches 1..3;
    // side[3] runs weight conversions.
    cudaStream_t side[4];
    cudaEvent_t e_fork, e_wq, e_rest, e_done[3];
    for (int i = 0; i < 4; i++)
        cudaStreamCreateWithFlags(&side[i], cudaStreamNonBlocking);
    cudaEventCreateWithFlags(&e_fork, cudaEventDisableTiming);
    cudaEventCreateWithFlags(&e_wq,   cudaEventDisableTiming);
    cudaEventCreateWithFlags(&e_rest, cudaEventDisableTiming);
    for (int i = 0; i < 3; i++)
        cudaEventCreateWithFlags(&e_done[i], cudaEventDisableTiming);

    // Fork
    cudaEventRecord(e_fork, 0);
    for (int i = 0; i < 4; i++) cudaStreamWaitEvent(side[i], e_fork, 0);

    // Weight conversions on side[3]
    cvt_w<<<(C3 * CC) / 1024, 256, 0, side[3]>>>(qkv_w, wq, (C3 * CC) / 4);
    cudaEventRecord(e_wq, side[3]);
    cvt3_w<<<(CVT3_TOTAL + 255) / 256, 256, 0, side[3]>>>(proj_w, fc1_w, fc2_w,
                                                          wp, w1, w2);
    cudaEventRecord(e_rest, side[3]);

    // Per-batch pipelines
    for (int b = 0; b < 4; b++) {
        cudaStream_t st = (b == 0) ? (cudaStream_t)0 : side[b - 1];
        const size_t rb = (size_t)b * MB;

        ln_kernel<<<MB / 8, 256, 0, st>>>(x + rb * CC, n1_w, n1_b, h1 + rb * CC);

        cudaStreamWaitEvent(st, e_wq, 0);
        gemm_tc<3><<<dim3(C3 / 64, MB / 128), 256, GEMM_SMEM_BYTES, st>>>(
            h1 + rb * CC, wq, nullptr, nullptr, nullptr, qv + rb * C3,
            MB, C3, CC);

        attn_tc<<<dim3(NN / 128, HH), 256, AT_SMEM_BYTES, st>>>(
            qv + rb * C3, rpb, at + rb * CC);

        cudaStreamWaitEvent(st, e_rest, 0);
        gemm_tc<1><<<dim3(CC / 64, MB / 128), 256, GEMM_SMEM_BYTES, st>>>(
            at + rb * CC, wp, proj_b, x + rb * CC, x1 + rb * CC, nullptr,
            MB, CC, CC);

        ln_kernel<<<MB / 8, 256, 0, st>>>(x1 + rb * CC, n2_w, n2_b, h2 + rb * CC);

        gemm_tc<2><<<dim3(HID / 64, MB / 128), 256, GEMM_SMEM_BYTES, st>>>(
            h2 + rb * CC, w1, fc1_b, nullptr, nullptr, hd + rb * HID,
            MB, HID, CC);

        gemm_tc<1><<<dim3(CC / 64, MB / 128), 256, GEMM_SMEM_BYTES, st>>>(
            hd + rb * HID, w2, fc2_b, x1 + rb * CC, out + rb * CC, nullptr,
            MB, CC, HID);

        if (b > 0) cudaEventRecord(e_done[b - 1], st);
    }

    // Join everything back into the main stream for graph capture.
    for (int i = 0; i < 3; i++) cudaStreamWaitEvent(0, e_done[i], 0);

    cudaEventDestroy(e_fork);
    cudaEventDestroy(e_wq);
    cudaEventDestroy(e_rest);
    for (int i = 0; i < 3; i++) cudaEventDestroy(e_done[i]);
    for (int i = 0; i < 4; i++) cudaStreamDestroy(side[i]);
}

// round 16
// speedup vs baseline: 1.2460x; 1.0486x over previous
#include <cuda_runtime.h>
#include <cuda_fp16.h>
#include <math.h>
#include <math_constants.h>
#include <stdint.h>

// Problem constants
#define BB    4
#define NN    2048
#define CC    512
#define HH    8
#define DH    64
#define HID   2048
#define MROWS (BB * NN)   // 8192
#define C3    (3 * CC)    // 1536
#define MB    NN          // rows per batch chunk (2048)

// ---------------------------------------------------------------------------
// Device scratch
// ---------------------------------------------------------------------------
__device__ float g_x1 [MROWS * CC];

__device__ __half g_qv[MROWS * C3];
__device__ __half g_h1[MROWS * CC];
__device__ __half g_at[MROWS * CC];
__device__ __half g_h2[MROWS * CC];
__device__ __half g_hd[MROWS * HID];

__device__ __half g_wq[C3 * CC];
__device__ __half g_wp[CC * CC];
__device__ __half g_w1[HID * CC];
__device__ __half g_w2[CC * HID];

// ---------------------------------------------------------------------------
// PTX helpers
// ---------------------------------------------------------------------------
__device__ __forceinline__ uint32_t smem_u32(const void* p) {
    uint32_t a;
    asm("{ .reg .u64 t; cvta.to.shared.u64 t, %1; cvt.u32.u64 %0, t; }"
        : "=r"(a) : "l"(p));
    return a;
}

#define CP16(dst, src)                                                        \
    asm volatile("cp.async.cg.shared.global [%0], [%1], 16;"                  \
                 :: "r"(dst), "l"(src))
#define CP4(dst, src)                                                         \
    asm volatile("cp.async.ca.shared.global [%0], [%1], 4;"                   \
                 :: "r"(dst), "l"(src))
#define CP_COMMIT() asm volatile("cp.async.commit_group;" ::: "memory")
#define CP_WAIT1()  asm volatile("cp.async.wait_group 1;" ::: "memory")
#define CP_WAIT0()  asm volatile("cp.async.wait_group 0;" ::: "memory")

__device__ __forceinline__ void ldsm4(uint32_t* r, uint32_t addr) {
    asm volatile("ldmatrix.sync.aligned.m8n8.x4.shared.b16 {%0,%1,%2,%3}, [%4];"
                 : "=r"(r[0]), "=r"(r[1]), "=r"(r[2]), "=r"(r[3]) : "r"(addr));
}

__device__ __forceinline__ void ldsm4t(uint32_t* r, uint32_t addr) {
    asm volatile("ldmatrix.sync.aligned.m8n8.x4.trans.shared.b16 {%0,%1,%2,%3}, [%4];"
                 : "=r"(r[0]), "=r"(r[1]), "=r"(r[2]), "=r"(r[3]) : "r"(addr));
}

__device__ __forceinline__ void mma16816(float* d, const uint32_t* a,
                                         uint32_t b0, uint32_t b1) {
    asm volatile(
        "mma.sync.aligned.m16n8k16.row.col.f32.f16.f16.f32 "
        "{%0,%1,%2,%3}, {%4,%5,%6,%7}, {%8,%9}, {%0,%1,%2,%3};"
        : "+f"(d[0]), "+f"(d[1]), "+f"(d[2]), "+f"(d[3])
        : "r"(a[0]), "r"(a[1]), "r"(a[2]), "r"(a[3]), "r"(b0), "r"(b1));
}

__device__ __forceinline__ uint32_t sw128(uint32_t off) {
    return off ^ ((off >> 3) & 0x70u);
}

__device__ __forceinline__ uint32_t pack_h2(float a, float b) {
    __half2 p = __floats2half2_rn(a, b);
    return *(uint32_t*)&p;
}

// ---------------------------------------------------------------------------
// Weight conversion
// ---------------------------------------------------------------------------
__global__ void cvt_w(const float* __restrict__ x, __half* __restrict__ hi,
                      int n4) {
    int i = blockIdx.x * blockDim.x + threadIdx.x;
    if (i >= n4) return;
    float4 v = *(const float4*)(x + 4 * (size_t)i);
    __half2 p0 = __floats2half2_rn(v.x, v.y);
    __half2 p1 = __floats2half2_rn(v.z, v.w);
    *(__half2*)(hi + 4 * (size_t)i)     = p0;
    *(__half2*)(hi + 4 * (size_t)i + 2) = p1;
}

#define WP_N4 ((CC * CC) / 4)
#define W1_N4 ((HID * CC) / 4)
#define W2_N4 ((CC * HID) / 4)
#define CVT3_TOTAL (WP_N4 + W1_N4 + W2_N4)

__global__ void cvt3_w(const float* __restrict__ wp_f,
                       const float* __restrict__ w1_f,
                       const float* __restrict__ w2_f,
                       __half* __restrict__ wp_h,
                       __half* __restrict__ w1_h,
                       __half* __restrict__ w2_h) {
    int i = blockIdx.x * blockDim.x + threadIdx.x;
    if (i >= CVT3_TOTAL) return;
    const float* src;
    __half* dst;
    int idx;
    if (i < WP_N4) {
        src = wp_f; dst = wp_h; idx = i;
    } else if (i < WP_N4 + W1_N4) {
        src = w1_f; dst = w1_h; idx = i - WP_N4;
    } else {
        src = w2_f; dst = w2_h; idx = i - WP_N4 - W1_N4;
    }
    float4 v = *(const float4*)(src + 4 * (size_t)idx);
    __half2 p0 = __floats2half2_rn(v.x, v.y);
    __half2 p1 = __floats2half2_rn(v.z, v.w);
    *(__half2*)(dst + 4 * (size_t)idx)     = p0;
    *(__half2*)(dst + 4 * (size_t)idx + 2) = p1;
}

// ---------------------------------------------------------------------------
// LayerNorm -> fp16.  One warp per row.
// ---------------------------------------------------------------------------
__global__ void ln_kernel(const float* __restrict__ x,
                          const float* __restrict__ w,
                          const float* __restrict__ b,
                          __half* __restrict__ ohi) {
    const int warp = threadIdx.x >> 5;
    const int lane = threadIdx.x & 31;
    const int row  = blockIdx.x * 8 + warp;
    const float* xr = x + (size_t)row * CC;

    float4 v[4];
    #pragma unroll
    for (int k = 0; k < 4; k++)
        v[k] = *(const float4*)(xr + (k * 32 + lane) * 4);

    float s = 0.f;
    #pragma unroll
    for (int k = 0; k < 4; k++) s += v[k].x + v[k].y + v[k].z + v[k].w;
    #pragma unroll
    for (int o = 16; o > 0; o >>= 1) s += __shfl_xor_sync(0xffffffffu, s, o);
    const float mean = s * (1.0f / CC);

    float s2 = 0.f;
    #pragma unroll
    for (int k = 0; k < 4; k++) {
        float d0 = v[k].x - mean, d1 = v[k].y - mean;
        float d2 = v[k].z - mean, d3 = v[k].w - mean;
        s2 += d0 * d0 + d1 * d1 + d2 * d2 + d3 * d3;
    }
    #pragma unroll
    for (int o = 16; o > 0; o >>= 1) s2 += __shfl_xor_sync(0xffffffffu, s2, o);
    const float inv = rsqrtf(s2 * (1.0f / CC) + 1e-5f);

    #pragma unroll
    for (int k = 0; k < 4; k++) {
        const int col = (k * 32 + lane) * 4;
        float4 wv = *(const float4*)(w + col);
        float4 bv = *(const float4*)(b + col);
        float y0 = (v[k].x - mean) * inv * wv.x + bv.x;
        float y1 = (v[k].y - mean) * inv * wv.y + bv.y;
        float y2 = (v[k].z - mean) * inv * wv.z + bv.z;
        float y3 = (v[k].w - mean) * inv * wv.w + bv.w;
        uint2 o;
        o.x = pack_h2(y0, y1);
        o.y = pack_h2(y2, y3);
        *(uint2*)(ohi + (size_t)row * CC + col) = o;
    }
}

// ---------------------------------------------------------------------------
// mma.sync 1-pass fp16 NT GEMM (128x128 CTA, 64x32 warp tiles, 3-stage).
// ---------------------------------------------------------------------------
#define GEMM_STAGE 32768
#define GEMM_SMEM_BYTES (3 * GEMM_STAGE)

__device__ __forceinline__ void load_chunk(
    const __half* __restrict__ A, const __half* __restrict__ B,
    int K, int m0, int n0, int kc, uint32_t sbuf, int tid) {
    #pragma unroll
    for (int j = 0; j < 8; j++) {
        const int linear = j * 256 + tid;
        const int arr = j >> 2;
        const int within = linear & 1023;
        const int r = within >> 3;
        const int c = within & 7;
        uint32_t sw = sw128((uint32_t)(r * 128 + c * 16));
        if (arr == 0) {
            CP16(sbuf + sw,
                 (const char*)(A + (size_t)(m0 + r) * K + (size_t)kc * 64 + c * 8));
        } else {
            CP16(sbuf + 16384 + sw,
                 (const char*)(B + (size_t)(n0 + r) * K + (size_t)kc * 64 + c * 8));
        }
    }
}

#define G_LOAD(KS, AF, BF) do {                                               \
    _Pragma("unroll")                                                         \
    for (int mi_ = 0; mi_ < 4; mi_++)                                         \
        ldsm4((AF)[mi_], aS + aoff[mi_] + ccol[KS]);                          \
    _Pragma("unroll")                                                         \
    for (int nj_ = 0; nj_ < 2; nj_++)                                         \
        ldsm4((BF)[nj_], bS + boff[nj_] + ccol[KS]);                          \
} while (0)

#define G_MMA(AF, BF) do {                                                    \
    _Pragma("unroll")                                                         \
    for (int mi_ = 0; mi_ < 4; mi_++) {                                       \
        _Pragma("unroll")                                                     \
        for (int nt_ = 0; nt_ < 4; nt_++) {                                   \
            const int nj_ = nt_ >> 1;                                         \
            const int p_  = nt_ & 1;                                          \
            mma16816(d[mi_][nt_], (AF)[mi_], (BF)[nj_][p_],                   \
                     (BF)[nj_][p_ + 2]);                                      \
        }                                                                     \
    }                                                                         \
} while (0)

template <int EPI>
__global__ __launch_bounds__(256, 2)
void gemm_tc(const __half* __restrict__ A,
             const __half* __restrict__ B,
             const float* __restrict__ bias,
             const float* __restrict__ res,
             float* __restrict__ outF,
             __half* __restrict__ outH,
             int M, int Nn, int K) {
    extern __shared__ char dsm[];
    const uint32_t bufs = smem_u32(dsm);

    const int tid  = threadIdx.x;
    const int wid  = tid >> 5;
    const int lane = tid & 31;

    const int m0 = blockIdx.y * 128;
    const int n0 = blockIdx.x * 128;
    const int NK = K >> 6;

    const int warp_m = (wid & 1) * 64;
    const int warp_n = (wid >> 1) * 32;

    const int lrow = lane & 7;
    const int sel  = lane >> 3;
    const int rofs = lrow + ((sel & 1) ? 8 : 0);
    const int kofs = (sel & 2) ? 8 : 0;

    const uint32_t rxor = (uint32_t)lrow << 4;
    uint32_t aoff[4], boff[2], ccol[4];
    #pragma unroll
    for (int mi = 0; mi < 4; mi++)
        aoff[mi] = (uint32_t)((warp_m + 16 * mi + rofs) * 128);
    #pragma unroll
    for (int nj = 0; nj < 2; nj++)
        boff[nj] = (uint32_t)((warp_n + 16 * nj + rofs) * 128);
    #pragma unroll
    for (int ks = 0; ks < 4; ks++)
        ccol[ks] = ((uint32_t)((ks * 16 + kofs) * 2)) ^ rxor;

    float d[4][4][4] = {};

    load_chunk(A, B, K, m0, n0, 0, bufs, tid);
    CP_COMMIT();
    load_chunk(A, B, K, m0, n0, 1, bufs + GEMM_STAGE, tid);
    CP_COMMIT();

    for (int kc = 0; kc < NK; kc++) {
        const uint32_t bufc = bufs + (kc % 3) * GEMM_STAGE;
        if (kc + 1 < NK) { CP_WAIT1(); } else { CP_WAIT0(); }
        __syncthreads();

        const uint32_t aS = bufc;
        const uint32_t bS = bufc + 16384;

        uint32_t af0[4][4], bf0[2][4], af1[4][4], bf1[2][4];
        G_LOAD(0, af0, bf0);
        G_LOAD(1, af1, bf1);
        G_MMA(af0, bf0);
        G_LOAD(2, af0, bf0);
        G_MMA(af1, bf1);
        G_LOAD(3, af1, bf1);
        G_MMA(af0, bf0);
        G_MMA(af1, bf1);

        if (kc + 2 < NK) {
            load_chunk(A, B, K, m0, n0, kc + 2,
                       bufs + ((kc + 2) % 3) * GEMM_STAGE, tid);
            CP_COMMIT();
        }
    }

    const int erow0 = m0 + warp_m + (lane >> 2);
    const int ecol0 = n0 + warp_n + (lane & 3) * 2;

    #pragma unroll
    for (int mi = 0; mi < 4; mi++) {
        #pragma unroll
        for (int nt = 0; nt < 4; nt++) {
            const int col = ecol0 + nt * 8;
            #pragma unroll
            for (int half = 0; half < 2; half++) {
                const int row = erow0 + mi * 16 + half * 8;
                float v0 = d[mi][nt][2 * half + 0];
                float v1 = d[mi][nt][2 * half + 1];
                const size_t ob = (size_t)row * Nn + col;
                if (EPI == 1) {
                    float2 rv = *(const float2*)(res + ob);
                    v0 += bias[col]     + rv.x;
                    v1 += bias[col + 1] + rv.y;
                    *(float2*)(outF + ob) = make_float2(v0, v1);
                } else if (EPI == 2) {
                    v0 += bias[col];
                    v1 += bias[col + 1];
                    float g0 = v0 * normcdff(v0);
                    float g1 = v1 * normcdff(v1);
                    *(__half2*)(outH + ob) = __floats2half2_rn(g0, g1);
                } else {
                    *(__half2*)(outH + ob) = __floats2half2_rn(v0, v1);
                }
            }
        }
    }
}

// ---------------------------------------------------------------------------
// Tensor-core flash attention (per-batch launch: grid = (NN/128, HH)).
// ---------------------------------------------------------------------------
#define AT_Q      0
#define AT_STAGE  16384
#define AT_BIAS   (16384 + 3 * 16384)
#define AT_SMEM_BYTES (AT_BIAS + 3 * 1024)

__device__ __forceinline__ void attn_prefetch(
    const __half* __restrict__ qv, const float* __restrict__ rpb,
    int h, int q0, int k0, uint32_t sbase, int s, int tid) {
    const uint32_t stage = sbase + AT_STAGE + s * 16384;
    #pragma unroll
    for (int j = 0; j < 4; j++) {
        int linear = tid + j * 256;
        int arr = linear >> 9;
        int within = linear & 511;
        int row = within >> 3;
        int c = within & 7;
        uint32_t dst = stage + arr * 8192 + sw128((uint32_t)(row * 128 + c * 16));
        int colbase = arr ? (2 * CC) : CC;
        CP16(dst, (const char*)(qv + (size_t)(k0 + row) * C3
                                + colbase + h * DH + c * 8));
    }
    if (tid < 192) {
        int idx = k0 - q0 + 1920 + tid;
        if (tid >= 191) idx = k0 - q0 + 1920;
        CP4(sbase + AT_BIAS + s * 1024 + tid * 4, rpb + (size_t)idx * HH + h);
    }
}

__global__ __launch_bounds__(256, 2)
void attn_tc(const __half* __restrict__ qv,
             const float* __restrict__ rpb,
             __half* __restrict__ outH) {
    extern __shared__ char dsm[];
    const uint32_t sbase = smem_u32(dsm);

    const int q0 = blockIdx.x * 128;
    const int h = blockIdx.y;

    const int tid  = threadIdx.x;
    const int wid  = tid >> 5;
    const int lane = tid & 31;

    const int lrow = lane & 7;
    const int sel  = lane >> 3;
    const int rofs = lrow + ((sel & 1) ? 8 : 0);
    const int kofs = (sel & 2) ? 8 : 0;

    const uint32_t rxor = (uint32_t)lrow << 4;
    uint32_t krow[4], ccol[4];
    #pragma unroll
    for (int np = 0; np < 4; np++)
        krow[np] = (uint32_t)((np * 16 + rofs) * 128);
    #pragma unroll
    for (int kc = 0; kc < 4; kc++)
        ccol[kc] = ((uint32_t)((kc * 16 + kofs) * 2)) ^ rxor;

    const int g  = lane >> 3;
    const int rr = lane & 7;
    uint32_t vrow[4], vcol[4];
    #pragma unroll
    for (int kc = 0; kc < 4; kc++)
        vrow[kc] = (uint32_t)((kc * 16 + (g & 1) * 8 + rr) * 128);
    #pragma unroll
    for (int dp = 0; dp < 4; dp++)
        vcol[dp] = ((uint32_t)(dp * 32 + (g >> 1) * 16)) ^ ((uint32_t)rr << 4);

    #pragma unroll
    for (int j = 0; j < 4; j++) {
        int linear = tid + j * 256;
        int row = linear >> 3;
        int c = linear & 7;
        uint32_t dst = sbase + AT_Q + sw128((uint32_t)(row * 128 + c * 16));
        CP16(dst, (const char*)(qv + (size_t)(q0 + row) * C3 + h * DH + c * 8));
    }
    attn_prefetch(qv, rpb, h, q0, 0, sbase, 0, tid);
    CP_COMMIT();
    attn_prefetch(qv, rpb, h, q0, 64, sbase, 1, tid);
    CP_COMMIT();

    uint32_t qf[4][4];
    float oacc[8][4] = {};
    float m0 = -CUDART_INF_F, m1 = -CUDART_INF_F;
    float l0 = 0.f, l1 = 0.f;

    const int NCHUNK = NN / 64;
    for (int c = 0; c < NCHUNK; c++) {
        const int s = c % 3;
        const uint32_t stage = sbase + AT_STAGE + s * 16384;
        const uint32_t bstage = sbase + AT_BIAS + s * 1024;
        if (c + 1 < NCHUNK) { CP_WAIT1(); } else { CP_WAIT0(); }
        __syncthreads();

        if (c == 0) {
            #pragma unroll
            for (int kc = 0; kc < 4; kc++)
                ldsm4(qf[kc], sbase + AT_Q
                      + (uint32_t)((wid * 16 + rofs) * 128) + ccol[kc]);
        }

        float sacc[8][4] = {};
        #pragma unroll
        for (int kc = 0; kc < 4; kc++) {
            uint32_t kfA[4], kfB[4];
            ldsm4(kfA, stage + krow[0] + ccol[kc]);
            ldsm4(kfB, stage + krow[1] + ccol[kc]);
            mma16816(sacc[0], qf[kc], kfA[0], kfA[2]);
            mma16816(sacc[1], qf[kc], kfA[1], kfA[3]);
            ldsm4(kfA, stage + krow[2] + ccol[kc]);
            mma16816(sacc[2], qf[kc], kfB[0], kfB[2]);
            mma16816(sacc[3], qf[kc], kfB[1], kfB[3]);
            ldsm4(kfB, stage + krow[3] + ccol[kc]);
            mma16816(sacc[4], qf[kc], kfA[0], kfA[2]);
            mma16816(sacc[5], qf[kc], kfA[1], kfA[3]);
            mma16816(sacc[6], qf[kc], kfB[0], kfB[2]);
            mma16816(sacc[7], qf[kc], kfB[1], kfB[3]);
        }

        const int r0 = wid * 16 + (lane >> 2);
        const int cb = (lane & 3) * 2;
        float mx0 = -CUDART_INF_F, mx1 = -CUDART_INF_F;
        #pragma unroll
        for (int nt = 0; nt < 8; nt++) {
            const int kk = nt * 8 + cb;
            float bv0, bv1, bv2, bv3;
            asm volatile("ld.shared.f32 %0, [%1];" : "=f"(bv0)
                         : "r"(bstage + (kk - r0 + 127) * 4));
            asm volatile("ld.shared.f32 %0, [%1];" : "=f"(bv1)
                         : "r"(bstage + (kk + 1 - r0 + 127) * 4));
            asm volatile("ld.shared.f32 %0, [%1];" : "=f"(bv2)
                         : "r"(bstage + (kk - (r0 + 8) + 127) * 4));
            asm volatile("ld.shared.f32 %0, [%1];" : "=f"(bv3)
                         : "r"(bstage + (kk + 1 - (r0 + 8) + 127) * 4));
            sacc[nt][0] = fmaf(sacc[nt][0], 0.125f, bv0);
            sacc[nt][1] = fmaf(sacc[nt][1], 0.125f, bv1);
            sacc[nt][2] = fmaf(sacc[nt][2], 0.125f, bv2);
            sacc[nt][3] = fmaf(sacc[nt][3], 0.125f, bv3);
            mx0 = fmaxf(mx0, fmaxf(sacc[nt][0], sacc[nt][1]));
            mx1 = fmaxf(mx1, fmaxf(sacc[nt][2], sacc[nt][3]));
        }
        mx0 = fmaxf(mx0, __shfl_xor_sync(0xffffffffu, mx0, 1));
        mx0 = fmaxf(mx0, __shfl_xor_sync(0xffffffffu, mx0, 2));
        mx1 = fmaxf(mx1, __shfl_xor_sync(0xffffffffu, mx1, 1));
        mx1 = fmaxf(mx1, __shfl_xor_sync(0xffffffffu, mx1, 2));
        const float mn0 = fmaxf(m0, mx0);
        const float mn1 = fmaxf(m1, mx1);
        const float fac0 = __expf(m0 - mn0);
        const float fac1 = __expf(m1 - mn1);
        float sum0 = 0.f, sum1 = 0.f;
        #pragma unroll
        for (int nt = 0; nt < 8; nt++) {
            sacc[nt][0] = __expf(sacc[nt][0] - mn0);
            sacc[nt][1] = __expf(sacc[nt][1] - mn0);
            sacc[nt][2] = __expf(sacc[nt][2] - mn1);
            sacc[nt][3] = __expf(sacc[nt][3] - mn1);
            sum0 += sacc[nt][0] + sacc[nt][1];
            sum1 += sacc[nt][2] + sacc[nt][3];
        }
        sum0 += __shfl_xor_sync(0xffffffffu, sum0, 1);
        sum0 += __shfl_xor_sync(0xffffffffu, sum0, 2);
        sum1 += __shfl_xor_sync(0xffffffffu, sum1, 1);
        sum1 += __shfl_xor_sync(0xffffffffu, sum1, 2);
        l0 = l0 * fac0 + sum0;
        l1 = l1 * fac1 + sum1;
        m0 = mn0;
        m1 = mn1;
        #pragma unroll
        for (int nt = 0; nt < 8; nt++) {
            oacc[nt][0] *= fac0;
            oacc[nt][1] *= fac0;
            oacc[nt][2] *= fac1;
            oacc[nt][3] *= fac1;
        }

        const uint32_t vbase = stage + 8192;
        #pragma unroll
        for (int kc = 0; kc < 4; kc++) {
            uint32_t pA[4];
            #pragma unroll
            for (int gg = 0; gg < 2; gg++) {
                const float* sv = sacc[2 * kc + gg];
                pA[2 * gg + 0] = pack_h2(sv[0], sv[1]);
                pA[2 * gg + 1] = pack_h2(sv[2], sv[3]);
            }
            uint32_t vfA[4], vfB[4];
            ldsm4t(vfA, vbase + vrow[kc] + vcol[0]);
            ldsm4t(vfB, vbase + vrow[kc] + vcol[1]);
            mma16816(oacc[0], pA, vfA[0], vfA[1]);
            mma16816(oacc[1], pA, vfA[2], vfA[3]);
            ldsm4t(vfA, vbase + vrow[kc] + vcol[2]);
            mma16816(oacc[2], pA, vfB[0], vfB[1]);
            mma16816(oacc[3], pA, vfB[2], vfB[3]);
            ldsm4t(vfB, vbase + vrow[kc] + vcol[3]);
            mma16816(oacc[4], pA, vfA[0], vfA[1]);
            mma16816(oacc[5], pA, vfA[2], vfA[3]);
            mma16816(oacc[6], pA, vfB[0], vfB[1]);
            mma16816(oacc[7], pA, vfB[2], vfB[3]);
        }

        if (c + 2 < NCHUNK) {
            attn_prefetch(qv, rpb, h, q0, (c + 2) * 64, sbase, (c + 2) % 3, tid);
            CP_COMMIT();
        }
    }

    const float il0 = 1.0f / l0;
    const float il1 = 1.0f / l1;
    const int row0 = q0 + wid * 16 + (lane >> 2);
    const int colb = h * DH + (lane & 3) * 2;
    #pragma unroll
    for (int nt = 0; nt < 8; nt++) {
        const int col = colb + nt * 8;
        *(__half2*)(outH + (size_t)row0 * CC + col) =
            __floats2half2_rn(oacc[nt][0] * il0, oacc[nt][1] * il0);
        *(__half2*)(outH + (size_t)(row0 + 8) * CC + col) =
            __floats2half2_rn(oacc[nt][2] * il1, oacc[nt][3] * il1);
    }
}

// ---------------------------------------------------------------------------
// Launcher — 4 independent per-batch pipelines on concurrent streams.
// ---------------------------------------------------------------------------
extern "C" void kernel_launch(void* const* d_in, const int* in_sizes, int n_in,
                              void* d_out, int out_size) {
    const float* x      = (const float*)d_in[0];
    const float* qkv_w  = (const float*)d_in[1];
    const float* proj_w = (const float*)d_in[2];
    const float* proj_b = (const float*)d_in[3];
    const float* rpb    = (const float*)d_in[4];
    const float* n1_w   = (const float*)d_in[5];
    const float* n1_b   = (const float*)d_in[6];
    const float* n2_w   = (const float*)d_in[7];
    const float* n2_b   = (const float*)d_in[8];
    const float* fc1_w  = (const float*)d_in[9];
    const float* fc1_b  = (const float*)d_in[10];
    const float* fc2_w  = (const float*)d_in[11];
    const float* fc2_b  = (const float*)d_in[12];
    float* out = (float*)d_out;

    float *x1;
    __half *qv, *h1, *at, *h2, *hd, *wq, *wp, *w1, *w2;
    cudaGetSymbolAddress((void**)&x1, g_x1);
    cudaGetSymbolAddress((void**)&qv, g_qv);
    cudaGetSymbolAddress((void**)&h1, g_h1);
    cudaGetSymbolAddress((void**)&at, g_at);
    cudaGetSymbolAddress((void**)&h2, g_h2);
    cudaGetSymbolAddress((void**)&hd, g_hd);
    cudaGetSymbolAddress((void**)&wq, g_wq);
    cudaGetSymbolAddress((void**)&wp, g_wp);
    cudaGetSymbolAddress((void**)&w1, g_w1);
    cudaGetSymbolAddress((void**)&w2, g_w2);

    cudaFuncSetAttribute(gemm_tc<1>, cudaFuncAttributeMaxDynamicSharedMemorySize, GEMM_SMEM_BYTES);
    cudaFuncSetAttribute(gemm_tc<2>, cudaFuncAttributeMaxDynamicSharedMemorySize, GEMM_SMEM_BYTES);
    cudaFuncSetAttribute(gemm_tc<3>, cudaFuncAttributeMaxDynamicSharedMemorySize, GEMM_SMEM_BYTES);
    cudaFuncSetAttribute(attn_tc, cudaFuncAttributeMaxDynamicSharedMemorySize, AT_SMEM_BYTES);

    // Streams: main (0) runs batch 0; side[0..2] run batches 1..3;
    // side[3] runs weight conversions.
    cudaStream_t side[4];
    cudaEvent_t e_fork, e_wq, e_rest, e_done[3];
    for (int i = 0; i < 4; i++)
        cudaStreamCreateWithFlags(&side[i], cudaStreamNonBlocking);
    cudaEventCreateWithFlags(&e_fork, cudaEventDisableTiming);
    cudaEventCreateWithFlags(&e_wq,   cudaEventDisableTiming);
    cudaEventCreateWithFlags(&e_rest, cudaEventDisableTiming);
    for (int i = 0; i < 3; i++)
        cudaEventCreateWithFlags(&e_done[i], cudaEventDisableTiming);

    // Fork
    cudaEventRecord(e_fork, 0);
    for (int i = 0; i < 4; i++) cudaStreamWaitEvent(side[i], e_fork, 0);

    // Weight conversions on side[3]
    cvt_w<<<(C3 * CC) / 1024, 256, 0, side[3]>>>(qkv_w, wq, (C3 * CC) / 4);
    cudaEventRecord(e_wq, side[3]);
    cvt3_w<<<(CVT3_TOTAL + 255) / 256, 256, 0, side[3]>>>(proj_w, fc1_w, fc2_w,
                                                          wp, w1, w2);
    cudaEventRecord(e_rest, side[3]);

    // Per-batch pipelines
    for (int b = 0; b < 4; b++) {
        cudaStream_t st = (b == 0) ? (cudaStream_t)0 : side[b - 1];
        const size_t rb = (size_t)b * MB;

        ln_kernel<<<MB / 8, 256, 0, st>>>(x + rb * CC, n1_w, n1_b, h1 + rb * CC);

        cudaStreamWaitEvent(st, e_wq, 0);
        gemm_tc<3><<<dim3(C3 / 128, MB / 128), 256, GEMM_SMEM_BYTES, st>>>(
            h1 + rb * CC, wq, nullptr, nullptr, nullptr, qv + rb * C3,
            MB, C3, CC);

        attn_tc<<<dim3(NN / 128, HH), 256, AT_SMEM_BYTES, st>>>(
            qv + rb * C3, rpb, at + rb * CC);

        cudaStreamWaitEvent(st, e_rest, 0);
        gemm_tc<1><<<dim3(CC / 128, MB / 128), 256, GEMM_SMEM_BYTES, st>>>(
            at + rb * CC, wp, proj_b, x + rb * CC, x1 + rb * CC, nullptr,
            MB, CC, CC);

        ln_kernel<<<MB / 8, 256, 0, st>>>(x1 + rb * CC, n2_w, n2_b, h2 + rb * CC);

        gemm_tc<2><<<dim3(HID / 128, MB / 128), 256, GEMM_SMEM_BYTES, st>>>(
            h2 + rb * CC, w1, fc1_b, nullptr, nullptr, hd + rb * HID,
            MB, HID, CC);

        gemm_tc<1><<<dim3(CC / 128, MB / 128), 256, GEMM_SMEM_BYTES, st>>>(
            hd + rb * HID, w2, fc2_b, x1 + rb * CC, out + rb * CC, nullptr,
            MB, CC, HID);

        if (b > 0) cudaEventRecord(e_done[b - 1], st);
    }

    // Join everything back into the main stream for graph capture.
    for (int i = 0; i < 3; i++) cudaStreamWaitEvent(0, e_done[i], 0);

    cudaEventDestroy(e_fork);
    cudaEventDestroy(e_wq);
    cudaEventDestroy(e_rest);
    for (int i = 0; i < 3; i++) cudaEventDestroy(e_done[i]);
    for (int i = 0; i < 4; i++) cudaStreamDestroy(side[i]);
}

// round 17
// speedup vs baseline: 1.2689x; 1.0184x over previous
#include <cuda_runtime.h>
#include <cuda_fp16.h>
#include <math.h>
#include <math_constants.h>
#include <stdint.h>

// Problem constants
#define BB    4
#define NN    2048
#define CC    512
#define HH    8
#define DH    64
#define HID   2048
#define MROWS (BB * NN)   // 8192
#define C3    (3 * CC)    // 1536
#define MB    NN          // rows per batch chunk (2048)

// ---------------------------------------------------------------------------
// Device scratch
// ---------------------------------------------------------------------------
__device__ float g_x1 [MROWS * CC];

__device__ __half g_qv[MROWS * C3];
__device__ __half g_h1[MROWS * CC];
__device__ __half g_at[MROWS * CC];
__device__ __half g_h2[MROWS * CC];
__device__ __half g_hd[MROWS * HID];

__device__ __half g_wq[C3 * CC];
__device__ __half g_wp[CC * CC];
__device__ __half g_w1[HID * CC];
__device__ __half g_w2[CC * HID];

// ---------------------------------------------------------------------------
// PTX helpers
// ---------------------------------------------------------------------------
__device__ __forceinline__ uint32_t smem_u32(const void* p) {
    uint32_t a;
    asm("{ .reg .u64 t; cvta.to.shared.u64 t, %1; cvt.u32.u64 %0, t; }"
        : "=r"(a) : "l"(p));
    return a;
}

#define CP16(dst, src)                                                        \
    asm volatile("cp.async.cg.shared.global [%0], [%1], 16;"                  \
                 :: "r"(dst), "l"(src))
#define CP4(dst, src)                                                         \
    asm volatile("cp.async.ca.shared.global [%0], [%1], 4;"                   \
                 :: "r"(dst), "l"(src))
#define CP_COMMIT() asm volatile("cp.async.commit_group;" ::: "memory")
#define CP_WAIT1()  asm volatile("cp.async.wait_group 1;" ::: "memory")
#define CP_WAIT0()  asm volatile("cp.async.wait_group 0;" ::: "memory")

__device__ __forceinline__ void ldsm4(uint32_t* r, uint32_t addr) {
    asm volatile("ldmatrix.sync.aligned.m8n8.x4.shared.b16 {%0,%1,%2,%3}, [%4];"
                 : "=r"(r[0]), "=r"(r[1]), "=r"(r[2]), "=r"(r[3]) : "r"(addr));
}

__device__ __forceinline__ void ldsm4t(uint32_t* r, uint32_t addr) {
    asm volatile("ldmatrix.sync.aligned.m8n8.x4.trans.shared.b16 {%0,%1,%2,%3}, [%4];"
                 : "=r"(r[0]), "=r"(r[1]), "=r"(r[2]), "=r"(r[3]) : "r"(addr));
}

__device__ __forceinline__ void mma16816(float* d, const uint32_t* a,
                                         uint32_t b0, uint32_t b1) {
    asm volatile(
        "mma.sync.aligned.m16n8k16.row.col.f32.f16.f16.f32 "
        "{%0,%1,%2,%3}, {%4,%5,%6,%7}, {%8,%9}, {%0,%1,%2,%3};"
        : "+f"(d[0]), "+f"(d[1]), "+f"(d[2]), "+f"(d[3])
        : "r"(a[0]), "r"(a[1]), "r"(a[2]), "r"(a[3]), "r"(b0), "r"(b1));
}

__device__ __forceinline__ uint32_t sw128(uint32_t off) {
    return off ^ ((off >> 3) & 0x70u);
}

__device__ __forceinline__ uint32_t pack_h2(float a, float b) {
    __half2 p = __floats2half2_rn(a, b);
    return *(uint32_t*)&p;
}

// One MUFU computes two exponentials (base-2, fp16x2).
__device__ __forceinline__ uint32_t ex2h2(uint32_t x) {
    uint32_t r;
    asm("ex2.approx.f16x2 %0, %1;" : "=r"(r) : "r"(x));
    return r;
}

// ---------------------------------------------------------------------------
// Weight conversion
// ---------------------------------------------------------------------------
__global__ void cvt_w(const float* __restrict__ x, __half* __restrict__ hi,
                      int n4) {
    int i = blockIdx.x * blockDim.x + threadIdx.x;
    if (i >= n4) return;
    float4 v = *(const float4*)(x + 4 * (size_t)i);
    __half2 p0 = __floats2half2_rn(v.x, v.y);
    __half2 p1 = __floats2half2_rn(v.z, v.w);
    *(__half2*)(hi + 4 * (size_t)i)     = p0;
    *(__half2*)(hi + 4 * (size_t)i + 2) = p1;
}

#define WP_N4 ((CC * CC) / 4)
#define W1_N4 ((HID * CC) / 4)
#define W2_N4 ((CC * HID) / 4)
#define CVT3_TOTAL (WP_N4 + W1_N4 + W2_N4)

__global__ void cvt3_w(const float* __restrict__ wp_f,
                       const float* __restrict__ w1_f,
                       const float* __restrict__ w2_f,
                       __half* __restrict__ wp_h,
                       __half* __restrict__ w1_h,
                       __half* __restrict__ w2_h) {
    int i = blockIdx.x * blockDim.x + threadIdx.x;
    if (i >= CVT3_TOTAL) return;
    const float* src;
    __half* dst;
    int idx;
    if (i < WP_N4) {
        src = wp_f; dst = wp_h; idx = i;
    } else if (i < WP_N4 + W1_N4) {
        src = w1_f; dst = w1_h; idx = i - WP_N4;
    } else {
        src = w2_f; dst = w2_h; idx = i - WP_N4 - W1_N4;
    }
    float4 v = *(const float4*)(src + 4 * (size_t)idx);
    __half2 p0 = __floats2half2_rn(v.x, v.y);
    __half2 p1 = __floats2half2_rn(v.z, v.w);
    *(__half2*)(dst + 4 * (size_t)idx)     = p0;
    *(__half2*)(dst + 4 * (size_t)idx + 2) = p1;
}

// ---------------------------------------------------------------------------
// LayerNorm -> fp16.  One warp per row.
// ---------------------------------------------------------------------------
__global__ void ln_kernel(const float* __restrict__ x,
                          const float* __restrict__ w,
                          const float* __restrict__ b,
                          __half* __restrict__ ohi) {
    const int warp = threadIdx.x >> 5;
    const int lane = threadIdx.x & 31;
    const int row  = blockIdx.x * 8 + warp;
    const float* xr = x + (size_t)row * CC;

    float4 v[4];
    #pragma unroll
    for (int k = 0; k < 4; k++)
        v[k] = *(const float4*)(xr + (k * 32 + lane) * 4);

    float s = 0.f;
    #pragma unroll
    for (int k = 0; k < 4; k++) s += v[k].x + v[k].y + v[k].z + v[k].w;
    #pragma unroll
    for (int o = 16; o > 0; o >>= 1) s += __shfl_xor_sync(0xffffffffu, s, o);
    const float mean = s * (1.0f / CC);

    float s2 = 0.f;
    #pragma unroll
    for (int k = 0; k < 4; k++) {
        float d0 = v[k].x - mean, d1 = v[k].y - mean;
        float d2 = v[k].z - mean, d3 = v[k].w - mean;
        s2 += d0 * d0 + d1 * d1 + d2 * d2 + d3 * d3;
    }
    #pragma unroll
    for (int o = 16; o > 0; o >>= 1) s2 += __shfl_xor_sync(0xffffffffu, s2, o);
    const float inv = rsqrtf(s2 * (1.0f / CC) + 1e-5f);

    #pragma unroll
    for (int k = 0; k < 4; k++) {
        const int col = (k * 32 + lane) * 4;
        float4 wv = *(const float4*)(w + col);
        float4 bv = *(const float4*)(b + col);
        float y0 = (v[k].x - mean) * inv * wv.x + bv.x;
        float y1 = (v[k].y - mean) * inv * wv.y + bv.y;
        float y2 = (v[k].z - mean) * inv * wv.z + bv.z;
        float y3 = (v[k].w - mean) * inv * wv.w + bv.w;
        uint2 o;
        o.x = pack_h2(y0, y1);
        o.y = pack_h2(y2, y3);
        *(uint2*)(ohi + (size_t)row * CC + col) = o;
    }
}

// ---------------------------------------------------------------------------
// mma.sync 1-pass fp16 NT GEMM (128x128 CTA, 64x32 warp tiles, 3-stage).
// ---------------------------------------------------------------------------
#define GEMM_STAGE 32768
#define GEMM_SMEM_BYTES (3 * GEMM_STAGE)

__device__ __forceinline__ void load_chunk(
    const __half* __restrict__ A, const __half* __restrict__ B,
    int K, int m0, int n0, int kc, uint32_t sbuf, int tid) {
    #pragma unroll
    for (int j = 0; j < 8; j++) {
        const int linear = j * 256 + tid;
        const int arr = j >> 2;
        const int within = linear & 1023;
        const int r = within >> 3;
        const int c = within & 7;
        uint32_t sw = sw128((uint32_t)(r * 128 + c * 16));
        if (arr == 0) {
            CP16(sbuf + sw,
                 (const char*)(A + (size_t)(m0 + r) * K + (size_t)kc * 64 + c * 8));
        } else {
            CP16(sbuf + 16384 + sw,
                 (const char*)(B + (size_t)(n0 + r) * K + (size_t)kc * 64 + c * 8));
        }
    }
}

#define G_LOAD(KS, AF, BF) do {                                               \
    _Pragma("unroll")                                                         \
    for (int mi_ = 0; mi_ < 4; mi_++)                                         \
        ldsm4((AF)[mi_], aS + aoff[mi_] + ccol[KS]);                          \
    _Pragma("unroll")                                                         \
    for (int nj_ = 0; nj_ < 2; nj_++)                                         \
        ldsm4((BF)[nj_], bS + boff[nj_] + ccol[KS]);                          \
} while (0)

#define G_MMA(AF, BF) do {                                                    \
    _Pragma("unroll")                                                         \
    for (int mi_ = 0; mi_ < 4; mi_++) {                                       \
        _Pragma("unroll")                                                     \
        for (int nt_ = 0; nt_ < 4; nt_++) {                                   \
            const int nj_ = nt_ >> 1;                                         \
            const int p_  = nt_ & 1;                                          \
            mma16816(d[mi_][nt_], (AF)[mi_], (BF)[nj_][p_],                   \
                     (BF)[nj_][p_ + 2]);                                      \
        }                                                                     \
    }                                                                         \
} while (0)

template <int EPI>
__global__ __launch_bounds__(256, 2)
void gemm_tc(const __half* __restrict__ A,
             const __half* __restrict__ B,
             const float* __restrict__ bias,
             const float* __restrict__ res,
             float* __restrict__ outF,
             __half* __restrict__ outH,
             int M, int Nn, int K) {
    extern __shared__ char dsm[];
    const uint32_t bufs = smem_u32(dsm);

    const int tid  = threadIdx.x;
    const int wid  = tid >> 5;
    const int lane = tid & 31;

    const int m0 = blockIdx.y * 128;
    const int n0 = blockIdx.x * 128;
    const int NK = K >> 6;

    const int warp_m = (wid & 1) * 64;
    const int warp_n = (wid >> 1) * 32;

    const int lrow = lane & 7;
    const int sel  = lane >> 3;
    const int rofs = lrow + ((sel & 1) ? 8 : 0);
    const int kofs = (sel & 2) ? 8 : 0;

    const uint32_t rxor = (uint32_t)lrow << 4;
    uint32_t aoff[4], boff[2], ccol[4];
    #pragma unroll
    for (int mi = 0; mi < 4; mi++)
        aoff[mi] = (uint32_t)((warp_m + 16 * mi + rofs) * 128);
    #pragma unroll
    for (int nj = 0; nj < 2; nj++)
        boff[nj] = (uint32_t)((warp_n + 16 * nj + rofs) * 128);
    #pragma unroll
    for (int ks = 0; ks < 4; ks++)
        ccol[ks] = ((uint32_t)((ks * 16 + kofs) * 2)) ^ rxor;

    float d[4][4][4] = {};

    load_chunk(A, B, K, m0, n0, 0, bufs, tid);
    CP_COMMIT();
    load_chunk(A, B, K, m0, n0, 1, bufs + GEMM_STAGE, tid);
    CP_COMMIT();

    for (int kc = 0; kc < NK; kc++) {
        const uint32_t bufc = bufs + (kc % 3) * GEMM_STAGE;
        if (kc + 1 < NK) { CP_WAIT1(); } else { CP_WAIT0(); }
        __syncthreads();

        const uint32_t aS = bufc;
        const uint32_t bS = bufc + 16384;

        uint32_t af0[4][4], bf0[2][4], af1[4][4], bf1[2][4];
        G_LOAD(0, af0, bf0);
        G_LOAD(1, af1, bf1);
        G_MMA(af0, bf0);
        G_LOAD(2, af0, bf0);
        G_MMA(af1, bf1);
        G_LOAD(3, af1, bf1);
        G_MMA(af0, bf0);
        G_MMA(af1, bf1);

        if (kc + 2 < NK) {
            load_chunk(A, B, K, m0, n0, kc + 2,
                       bufs + ((kc + 2) % 3) * GEMM_STAGE, tid);
            CP_COMMIT();
        }
    }

    const int erow0 = m0 + warp_m + (lane >> 2);
    const int ecol0 = n0 + warp_n + (lane & 3) * 2;

    #pragma unroll
    for (int mi = 0; mi < 4; mi++) {
        #pragma unroll
        for (int nt = 0; nt < 4; nt++) {
            const int col = ecol0 + nt * 8;
            #pragma unroll
            for (int half = 0; half < 2; half++) {
                const int row = erow0 + mi * 16 + half * 8;
                float v0 = d[mi][nt][2 * half + 0];
                float v1 = d[mi][nt][2 * half + 1];
                const size_t ob = (size_t)row * Nn + col;
                if (EPI == 1) {
                    float2 rv = *(const float2*)(res + ob);
                    v0 += bias[col]     + rv.x;
                    v1 += bias[col + 1] + rv.y;
                    *(float2*)(outF + ob) = make_float2(v0, v1);
                } else if (EPI == 2) {
                    v0 += bias[col];
                    v1 += bias[col + 1];
                    float g0 = v0 * normcdff(v0);
                    float g1 = v1 * normcdff(v1);
                    *(__half2*)(outH + ob) = __floats2half2_rn(g0, g1);
                } else {
                    *(__half2*)(outH + ob) = __floats2half2_rn(v0, v1);
                }
            }
        }
    }
}

// ---------------------------------------------------------------------------
// Tensor-core flash attention (per-batch launch: grid = (NN/128, HH)).
// Softmax exponentials via ex2.approx.f16x2: half the MUFU issue, and the
// fp16 result IS the PV mma A-fragment (no separate pack).
// ---------------------------------------------------------------------------
#define AT_Q      0
#define AT_STAGE  16384
#define AT_BIAS   (16384 + 3 * 16384)
#define AT_SMEM_BYTES (AT_BIAS + 3 * 1024)

__device__ __forceinline__ void attn_prefetch(
    const __half* __restrict__ qv, const float* __restrict__ rpb,
    int h, int q0, int k0, uint32_t sbase, int s, int tid) {
    const uint32_t stage = sbase + AT_STAGE + s * 16384;
    #pragma unroll
    for (int j = 0; j < 4; j++) {
        int linear = tid + j * 256;
        int arr = linear >> 9;
        int within = linear & 511;
        int row = within >> 3;
        int c = within & 7;
        uint32_t dst = stage + arr * 8192 + sw128((uint32_t)(row * 128 + c * 16));
        int colbase = arr ? (2 * CC) : CC;
        CP16(dst, (const char*)(qv + (size_t)(k0 + row) * C3
                                + colbase + h * DH + c * 8));
    }
    if (tid < 192) {
        int idx = k0 - q0 + 1920 + tid;
        if (tid >= 191) idx = k0 - q0 + 1920;
        CP4(sbase + AT_BIAS + s * 1024 + tid * 4, rpb + (size_t)idx * HH + h);
    }
}

__global__ __launch_bounds__(256, 2)
void attn_tc(const __half* __restrict__ qv,
             const float* __restrict__ rpb,
             __half* __restrict__ outH) {
    extern __shared__ char dsm[];
    const uint32_t sbase = smem_u32(dsm);

    const int q0 = blockIdx.x * 128;
    const int h = blockIdx.y;

    const int tid  = threadIdx.x;
    const int wid  = tid >> 5;
    const int lane = tid & 31;

    const int lrow = lane & 7;
    const int sel  = lane >> 3;
    const int rofs = lrow + ((sel & 1) ? 8 : 0);
    const int kofs = (sel & 2) ? 8 : 0;

    const uint32_t rxor = (uint32_t)lrow << 4;
    uint32_t krow[4], ccol[4];
    #pragma unroll
    for (int np = 0; np < 4; np++)
        krow[np] = (uint32_t)((np * 16 + rofs) * 128);
    #pragma unroll
    for (int kc = 0; kc < 4; kc++)
        ccol[kc] = ((uint32_t)((kc * 16 + kofs) * 2)) ^ rxor;

    const int g  = lane >> 3;
    const int rr = lane & 7;
    uint32_t vrow[4], vcol[4];
    #pragma unroll
    for (int kc = 0; kc < 4; kc++)
        vrow[kc] = (uint32_t)((kc * 16 + (g & 1) * 8 + rr) * 128);
    #pragma unroll
    for (int dp = 0; dp < 4; dp++)
        vcol[dp] = ((uint32_t)(dp * 32 + (g >> 1) * 16)) ^ ((uint32_t)rr << 4);

    #pragma unroll
    for (int j = 0; j < 4; j++) {
        int linear = tid + j * 256;
        int row = linear >> 3;
        int c = linear & 7;
        uint32_t dst = sbase + AT_Q + sw128((uint32_t)(row * 128 + c * 16));
        CP16(dst, (const char*)(qv + (size_t)(q0 + row) * C3 + h * DH + c * 8));
    }
    attn_prefetch(qv, rpb, h, q0, 0, sbase, 0, tid);
    CP_COMMIT();
    attn_prefetch(qv, rpb, h, q0, 64, sbase, 1, tid);
    CP_COMMIT();

    uint32_t qf[4][4];
    float oacc[8][4] = {};
    float m0 = -CUDART_INF_F, m1 = -CUDART_INF_F;
    float l0 = 0.f, l1 = 0.f;
    const float L2E = 1.4426950408889634f;

    const int NCHUNK = NN / 64;
    for (int c = 0; c < NCHUNK; c++) {
        const int s = c % 3;
        const uint32_t stage = sbase + AT_STAGE + s * 16384;
        const uint32_t bstage = sbase + AT_BIAS + s * 1024;
        if (c + 1 < NCHUNK) { CP_WAIT1(); } else { CP_WAIT0(); }
        __syncthreads();

        if (c == 0) {
            #pragma unroll
            for (int kc = 0; kc < 4; kc++)
                ldsm4(qf[kc], sbase + AT_Q
                      + (uint32_t)((wid * 16 + rofs) * 128) + ccol[kc]);
        }

        // ---- S = Q K^T ----
        float sacc[8][4] = {};
        #pragma unroll
        for (int kc = 0; kc < 4; kc++) {
            uint32_t kfA[4], kfB[4];
            ldsm4(kfA, stage + krow[0] + ccol[kc]);
            ldsm4(kfB, stage + krow[1] + ccol[kc]);
            mma16816(sacc[0], qf[kc], kfA[0], kfA[2]);
            mma16816(sacc[1], qf[kc], kfA[1], kfA[3]);
            ldsm4(kfA, stage + krow[2] + ccol[kc]);
            mma16816(sacc[2], qf[kc], kfB[0], kfB[2]);
            mma16816(sacc[3], qf[kc], kfB[1], kfB[3]);
            ldsm4(kfB, stage + krow[3] + ccol[kc]);
            mma16816(sacc[4], qf[kc], kfA[0], kfA[2]);
            mma16816(sacc[5], qf[kc], kfA[1], kfA[3]);
            mma16816(sacc[6], qf[kc], kfB[0], kfB[2]);
            mma16816(sacc[7], qf[kc], kfB[1], kfB[3]);
        }

        // ---- bias + online softmax (base-2, fp16x2 exponentials) ----
        const int r0 = wid * 16 + (lane >> 2);
        const int cb = (lane & 3) * 2;
        float mx0 = -CUDART_INF_F, mx1 = -CUDART_INF_F;
        #pragma unroll
        for (int nt = 0; nt < 8; nt++) {
            const int kk = nt * 8 + cb;
            float bv0, bv1, bv2, bv3;
            asm volatile("ld.shared.f32 %0, [%1];" : "=f"(bv0)
                         : "r"(bstage + (kk - r0 + 127) * 4));
            asm volatile("ld.shared.f32 %0, [%1];" : "=f"(bv1)
                         : "r"(bstage + (kk + 1 - r0 + 127) * 4));
            asm volatile("ld.shared.f32 %0, [%1];" : "=f"(bv2)
                         : "r"(bstage + (kk - (r0 + 8) + 127) * 4));
            asm volatile("ld.shared.f32 %0, [%1];" : "=f"(bv3)
                         : "r"(bstage + (kk + 1 - (r0 + 8) + 127) * 4));
            sacc[nt][0] = fmaf(sacc[nt][0], 0.125f, bv0);
            sacc[nt][1] = fmaf(sacc[nt][1], 0.125f, bv1);
            sacc[nt][2] = fmaf(sacc[nt][2], 0.125f, bv2);
            sacc[nt][3] = fmaf(sacc[nt][3], 0.125f, bv3);
            mx0 = fmaxf(mx0, fmaxf(sacc[nt][0], sacc[nt][1]));
            mx1 = fmaxf(mx1, fmaxf(sacc[nt][2], sacc[nt][3]));
        }
        mx0 = fmaxf(mx0, __shfl_xor_sync(0xffffffffu, mx0, 1));
        mx0 = fmaxf(mx0, __shfl_xor_sync(0xffffffffu, mx0, 2));
        mx1 = fmaxf(mx1, __shfl_xor_sync(0xffffffffu, mx1, 1));
        mx1 = fmaxf(mx1, __shfl_xor_sync(0xffffffffu, mx1, 2));
        const float mn0 = fmaxf(m0, mx0);
        const float mn1 = fmaxf(m1, mx1);
        const float fac0 = __expf(m0 - mn0);
        const float fac1 = __expf(m1 - mn1);
        const float nm0 = -mn0 * L2E;
        const float nm1 = -mn1 * L2E;

        uint32_t pLo[8], pHi[8];
        float sum0 = 0.f, sum1 = 0.f;
        #pragma unroll
        for (int nt = 0; nt < 8; nt++) {
            uint32_t a = pack_h2(fmaf(sacc[nt][0], L2E, nm0),
                                 fmaf(sacc[nt][1], L2E, nm0));
            uint32_t bq = pack_h2(fmaf(sacc[nt][2], L2E, nm1),
                                  fmaf(sacc[nt][3], L2E, nm1));
            a  = ex2h2(a);
            bq = ex2h2(bq);
            pLo[nt] = a;
            pHi[nt] = bq;
            float2 fa = __half22float2(*(__half2*)&a);
            float2 fb = __half22float2(*(__half2*)&bq);
            sum0 += fa.x + fa.y;
            sum1 += fb.x + fb.y;
        }
        sum0 += __shfl_xor_sync(0xffffffffu, sum0, 1);
        sum0 += __shfl_xor_sync(0xffffffffu, sum0, 2);
        sum1 += __shfl_xor_sync(0xffffffffu, sum1, 1);
        sum1 += __shfl_xor_sync(0xffffffffu, sum1, 2);
        l0 = l0 * fac0 + sum0;
        l1 = l1 * fac1 + sum1;
        m0 = mn0;
        m1 = mn1;
        #pragma unroll
        for (int nt = 0; nt < 8; nt++) {
            oacc[nt][0] *= fac0;
            oacc[nt][1] *= fac0;
            oacc[nt][2] *= fac1;
            oacc[nt][3] *= fac1;
        }

        // ---- O += P V  (P fragments are the ex2 outputs directly) ----
        const uint32_t vbase = stage + 8192;
        #pragma unroll
        for (int kc = 0; kc < 4; kc++) {
            uint32_t pA[4];
            pA[0] = pLo[2 * kc + 0];
            pA[1] = pHi[2 * kc + 0];
            pA[2] = pLo[2 * kc + 1];
            pA[3] = pHi[2 * kc + 1];
            uint32_t vfA[4], vfB[4];
            ldsm4t(vfA, vbase + vrow[kc] + vcol[0]);
            ldsm4t(vfB, vbase + vrow[kc] + vcol[1]);
            mma16816(oacc[0], pA, vfA[0], vfA[1]);
            mma16816(oacc[1], pA, vfA[2], vfA[3]);
            ldsm4t(vfA, vbase + vrow[kc] + vcol[2]);
            mma16816(oacc[2], pA, vfB[0], vfB[1]);
            mma16816(oacc[3], pA, vfB[2], vfB[3]);
            ldsm4t(vfB, vbase + vrow[kc] + vcol[3]);
            mma16816(oacc[4], pA, vfA[0], vfA[1]);
            mma16816(oacc[5], pA, vfA[2], vfA[3]);
            mma16816(oacc[6], pA, vfB[0], vfB[1]);
            mma16816(oacc[7], pA, vfB[2], vfB[3]);
        }

        if (c + 2 < NCHUNK) {
            attn_prefetch(qv, rpb, h, q0, (c + 2) * 64, sbase, (c + 2) % 3, tid);
            CP_COMMIT();
        }
    }

    const float il0 = 1.0f / l0;
    const float il1 = 1.0f / l1;
    const int row0 = q0 + wid * 16 + (lane >> 2);
    const int colb = h * DH + (lane & 3) * 2;
    #pragma unroll
    for (int nt = 0; nt < 8; nt++) {
        const int col = colb + nt * 8;
        *(__half2*)(outH + (size_t)row0 * CC + col) =
            __floats2half2_rn(oacc[nt][0] * il0, oacc[nt][1] * il0);
        *(__half2*)(outH + (size_t)(row0 + 8) * CC + col) =
            __floats2half2_rn(oacc[nt][2] * il1, oacc[nt][3] * il1);
    }
}

// ---------------------------------------------------------------------------
// Launcher — 4 independent per-batch pipelines on concurrent streams.
// ---------------------------------------------------------------------------
extern "C" void kernel_launch(void* const* d_in, const int* in_sizes, int n_in,
                              void* d_out, int out_size) {
    const float* x      = (const float*)d_in[0];
    const float* qkv_w  = (const float*)d_in[1];
    const float* proj_w = (const float*)d_in[2];
    const float* proj_b = (const float*)d_in[3];
    const float* rpb    = (const float*)d_in[4];
    const float* n1_w   = (const float*)d_in[5];
    const float* n1_b   = (const float*)d_in[6];
    const float* n2_w   = (const float*)d_in[7];
    const float* n2_b   = (const float*)d_in[8];
    const float* fc1_w  = (const float*)d_in[9];
    const float* fc1_b  = (const float*)d_in[10];
    const float* fc2_w  = (const float*)d_in[11];
    const float* fc2_b  = (const float*)d_in[12];
    float* out = (float*)d_out;

    float *x1;
    __half *qv, *h1, *at, *h2, *hd, *wq, *wp, *w1, *w2;
    cudaGetSymbolAddress((void**)&x1, g_x1);
    cudaGetSymbolAddress((void**)&qv, g_qv);
    cudaGetSymbolAddress((void**)&h1, g_h1);
    cudaGetSymbolAddress((void**)&at, g_at);
    cudaGetSymbolAddress((void**)&h2, g_h2);
    cudaGetSymbolAddress((void**)&hd, g_hd);
    cudaGetSymbolAddress((void**)&wq, g_wq);
    cudaGetSymbolAddress((void**)&wp, g_wp);
    cudaGetSymbolAddress((void**)&w1, g_w1);
    cudaGetSymbolAddress((void**)&w2, g_w2);

    cudaFuncSetAttribute(gemm_tc<1>, cudaFuncAttributeMaxDynamicSharedMemorySize, GEMM_SMEM_BYTES);
    cudaFuncSetAttribute(gemm_tc<2>, cudaFuncAttributeMaxDynamicSharedMemorySize, GEMM_SMEM_BYTES);
    cudaFuncSetAttribute(gemm_tc<3>, cudaFuncAttributeMaxDynamicSharedMemorySize, GEMM_SMEM_BYTES);
    cudaFuncSetAttribute(attn_tc, cudaFuncAttributeMaxDynamicSharedMemorySize, AT_SMEM_BYTES);

    // Streams: main (0) runs batch 0; side[0..2] run batches 1..3;
    // side[3] runs weight conversions.
    cudaStream_t side[4];
    cudaEvent_t e_fork, e_wq, e_rest, e_done[3];
    for (int i = 0; i < 4; i++)
        cudaStreamCreateWithFlags(&side[i], cudaStreamNonBlocking);
    cudaEventCreateWithFlags(&e_fork, cudaEventDisableTiming);
    cudaEventCreateWithFlags(&e_wq,   cudaEventDisableTiming);
    cudaEventCreateWithFlags(&e_rest, cudaEventDisableTiming);
    for (int i = 0; i < 3; i++)
        cudaEventCreateWithFlags(&e_done[i], cudaEventDisableTiming);

    // Fork
    cudaEventRecord(e_fork, 0);
    for (int i = 0; i < 4; i++) cudaStreamWaitEvent(side[i], e_fork, 0);

    // Weight conversions on side[3]
    cvt_w<<<(C3 * CC) / 1024, 256, 0, side[3]>>>(qkv_w, wq, (C3 * CC) / 4);
    cudaEventRecord(e_wq, side[3]);
    cvt3_w<<<(CVT3_TOTAL + 255) / 256, 256, 0, side[3]>>>(proj_w, fc1_w, fc2_w,
                                                          wp, w1, w2);
    cudaEventRecord(e_rest, side[3]);

    // Per-batch pipelines
    for (int b = 0; b < 4; b++) {
        cudaStream_t st = (b == 0) ? (cudaStream_t)0 : side[b - 1];
        const size_t rb = (size_t)b * MB;

        ln_kernel<<<MB / 8, 256, 0, st>>>(x + rb * CC, n1_w, n1_b, h1 + rb * CC);

        cudaStreamWaitEvent(st, e_wq, 0);
        gemm_tc<3><<<dim3(C3 / 128, MB / 128), 256, GEMM_SMEM_BYTES, st>>>(
            h1 + rb * CC, wq, nullptr, nullptr, nullptr, qv + rb * C3,
            MB, C3, CC);

        attn_tc<<<dim3(NN / 128, HH), 256, AT_SMEM_BYTES, st>>>(
            qv + rb * C3, rpb, at + rb * CC);

        cudaStreamWaitEvent(st, e_rest, 0);
        gemm_tc<1><<<dim3(CC / 128, MB / 128), 256, GEMM_SMEM_BYTES, st>>>(
            at + rb * CC, wp, proj_b, x + rb * CC, x1 + rb * CC, nullptr,
            MB, CC, CC);

        ln_kernel<<<MB / 8, 256, 0, st>>>(x1 + rb * CC, n2_w, n2_b, h2 + rb * CC);

        gemm_tc<2><<<dim3(HID / 128, MB / 128), 256, GEMM_SMEM_BYTES, st>>>(
            h2 + rb * CC, w1, fc1_b, nullptr, nullptr, hd + rb * HID,
            MB, HID, CC);

        gemm_tc<1><<<dim3(CC / 128, MB / 128), 256, GEMM_SMEM_BYTES, st>>>(
            hd + rb * HID, w2, fc2_b, x1 + rb * CC, out + rb * CC, nullptr,
            MB, CC, HID);

        if (b > 0) cudaEventRecord(e_done[b - 1], st);
    }

    // Join everything back into the main stream for graph capture.
    for (int i = 0; i < 3; i++) cudaStreamWaitEvent(0, e_done[i], 0);

    cudaEventDestroy(e_fork);
    cudaEventDestroy(e_wq);
    cudaEventDestroy(e_rest);
    for (int i = 0; i < 3; i++) cudaEventDestroy(e_done[i]);
    for (int i = 0; i < 4; i++) cudaStreamDestroy(side[i]);
}